// round 1
// baseline (speedup 1.0000x reference)
#include <cuda_runtime.h>

#define F        128
#define TM       128
#define NTHREADS 256
#define N_ATOMS  8192

// Scratch (device globals: no allocations allowed)
__device__ float g_PS[N_ATOMS * F];   // segment-summed pair activations
__device__ float g_AA[N_ATOMS * F];   // atom-branch layer-1 output

// ---------------------------------------------------------------------------
// vectorized global reduction (sm_90+): 4 floats per op, 16B-aligned address
// ---------------------------------------------------------------------------
__device__ __forceinline__ void red_v4(float* addr, float a, float b, float c, float d) {
    asm volatile("red.global.add.v4.f32 [%0], {%1,%2,%3,%4};"
                 :: "l"(addr), "f"(a), "f"(b), "f"(c), "f"(d) : "memory");
}

// ---------------------------------------------------------------------------
// Shared inner GEMM block: 128x128 X-tile (row-major in smem) times two
// 128x128 weight tiles (k-major in smem). Each thread owns an 8-row x
// (8+8)-col register tile at (r0, c0).
// ---------------------------------------------------------------------------
__device__ __forceinline__ void gemm_block(const float* __restrict__ Wa_s,
                                           const float* __restrict__ Wb_s,
                                           const float* __restrict__ Xs,
                                           int r0, int c0,
                                           float acc_a[8][8], float acc_b[8][8]) {
#pragma unroll 1
    for (int k = 0; k < F; k += 4) {
        float4 af[8];
#pragma unroll
        for (int i = 0; i < 8; i++)
            af[i] = *(const float4*)(Xs + (r0 + i) * F + k);
#pragma unroll
        for (int kk = 0; kk < 4; kk++) {
            const float4 wa0 = *(const float4*)(Wa_s + (k + kk) * F + c0);
            const float4 wa1 = *(const float4*)(Wa_s + (k + kk) * F + c0 + 4);
            const float4 wb0 = *(const float4*)(Wb_s + (k + kk) * F + c0);
            const float4 wb1 = *(const float4*)(Wb_s + (k + kk) * F + c0 + 4);
            const float wa[8] = {wa0.x, wa0.y, wa0.z, wa0.w, wa1.x, wa1.y, wa1.z, wa1.w};
            const float wb[8] = {wb0.x, wb0.y, wb0.z, wb0.w, wb1.x, wb1.y, wb1.z, wb1.w};
#pragma unroll
            for (int i = 0; i < 8; i++) {
                const float av = (kk == 0) ? af[i].x
                               : (kk == 1) ? af[i].y
                               : (kk == 2) ? af[i].z : af[i].w;
#pragma unroll
                for (int j = 0; j < 8; j++) {
                    acc_a[i][j] = fmaf(av, wa[j], acc_a[i][j]);
                    acc_b[i][j] = fmaf(av, wb[j], acc_b[i][j]);
                }
            }
        }
    }
}

// ---------------------------------------------------------------------------
// Zero the pair-sum accumulator
// ---------------------------------------------------------------------------
extern "C" __global__ void eaw_zero_ps() {
    const int i = blockIdx.x * blockDim.x + threadIdx.x;
    ((float4*)g_PS)[i] = make_float4(0.f, 0.f, 0.f, 0.f);
}

// ---------------------------------------------------------------------------
// Pair branch: PA = relu(t2 * (FP@W2a+b2a) * (FP@W2b+b2b)); scatter-add by atom
// Persistent CTAs, weights resident in smem.
// ---------------------------------------------------------------------------
extern "C" __global__ void __launch_bounds__(NTHREADS, 1)
eaw_pair_kernel(const float* __restrict__ FP, const int* __restrict__ split,
                const float* __restrict__ W2a, const float* __restrict__ b2a,
                const float* __restrict__ W2b, const float* __restrict__ b2b,
                const float* __restrict__ t2, int nTiles) {
    extern __shared__ float sm[];
    float* Wa_s = sm;              // 128*128
    float* Wb_s = sm + 16384;      // 128*128
    float* Xs   = sm + 32768;      // 128*128

    const int tid = threadIdx.x;
    for (int i = tid; i < 4096; i += NTHREADS) {
        ((float4*)Wa_s)[i] = ((const float4*)W2a)[i];
        ((float4*)Wb_s)[i] = ((const float4*)W2b)[i];
    }

    const int tr = tid >> 4, tc = tid & 15;
    const int r0 = tr * 8, c0 = tc * 8;

    for (int tile = blockIdx.x; tile < nTiles; tile += gridDim.x) {
        const int rowBase = tile * TM;
        __syncthreads();  // smem reuse guard (also orders weight loads on iter 0)
        {
            const float4* src = (const float4*)(FP + (size_t)rowBase * F);
            for (int i = tid; i < 4096; i += NTHREADS) ((float4*)Xs)[i] = src[i];
        }
        __syncthreads();

        float acc_a[8][8], acc_b[8][8];
#pragma unroll
        for (int j = 0; j < 8; j++) {
            const float bav = b2a[c0 + j], bbv = b2b[c0 + j];
#pragma unroll
            for (int i = 0; i < 8; i++) { acc_a[i][j] = bav; acc_b[i][j] = bbv; }
        }

        gemm_block(Wa_s, Wb_s, Xs, r0, c0, acc_a, acc_b);

        // epilogue: relu(t2 * ya * yb), scatter-add into g_PS[atom]
        float tv[8];
#pragma unroll
        for (int j = 0; j < 8; j++) tv[j] = t2[c0 + j];
#pragma unroll
        for (int i = 0; i < 8; i++) {
            const int row  = rowBase + r0 + i;
            const int atom = split[row];
            float* dst = g_PS + (size_t)atom * F + c0;
            float o[8];
#pragma unroll
            for (int j = 0; j < 8; j++) {
                const float v = tv[j] * acc_a[i][j] * acc_b[i][j];
                o[j] = fmaxf(v, 0.f);
            }
            red_v4(dst,     o[0], o[1], o[2], o[3]);
            red_v4(dst + 4, o[4], o[5], o[6], o[7]);
        }
    }
}

// ---------------------------------------------------------------------------
// Atom branch layer 1: g_AA = relu(t1 * (FA@W1a+b1a) * (FA@W1b+b1b))
// One CTA per 128-row tile.
// ---------------------------------------------------------------------------
extern "C" __global__ void __launch_bounds__(NTHREADS, 1)
eaw_atom1_kernel(const float* __restrict__ FA,
                 const float* __restrict__ W1a, const float* __restrict__ b1a,
                 const float* __restrict__ W1b, const float* __restrict__ b1b,
                 const float* __restrict__ t1) {
    extern __shared__ float sm[];
    float* Wa_s = sm;
    float* Wb_s = sm + 16384;
    float* Xs   = sm + 32768;

    const int tid = threadIdx.x;
    const int rowBase = blockIdx.x * TM;
    {
        const float4* src = (const float4*)(FA + (size_t)rowBase * F);
        for (int i = tid; i < 4096; i += NTHREADS) {
            ((float4*)Wa_s)[i] = ((const float4*)W1a)[i];
            ((float4*)Wb_s)[i] = ((const float4*)W1b)[i];
            ((float4*)Xs)[i]   = src[i];
        }
    }
    __syncthreads();

    const int tr = tid >> 4, tc = tid & 15;
    const int r0 = tr * 8, c0 = tc * 8;

    float acc_a[8][8], acc_b[8][8];
#pragma unroll
    for (int j = 0; j < 8; j++) {
        const float bav = b1a[c0 + j], bbv = b1b[c0 + j];
#pragma unroll
        for (int i = 0; i < 8; i++) { acc_a[i][j] = bav; acc_b[i][j] = bbv; }
    }

    gemm_block(Wa_s, Wb_s, Xs, r0, c0, acc_a, acc_b);

    float tv[8];
#pragma unroll
    for (int j = 0; j < 8; j++) tv[j] = t1[c0 + j];
#pragma unroll
    for (int i = 0; i < 8; i++) {
        const int row = rowBase + r0 + i;
        float4 v0, v1;
        v0.x = fmaxf(tv[0] * acc_a[i][0] * acc_b[i][0], 0.f);
        v0.y = fmaxf(tv[1] * acc_a[i][1] * acc_b[i][1], 0.f);
        v0.z = fmaxf(tv[2] * acc_a[i][2] * acc_b[i][2], 0.f);
        v0.w = fmaxf(tv[3] * acc_a[i][3] * acc_b[i][3], 0.f);
        v1.x = fmaxf(tv[4] * acc_a[i][4] * acc_b[i][4], 0.f);
        v1.y = fmaxf(tv[5] * acc_a[i][5] * acc_b[i][5], 0.f);
        v1.z = fmaxf(tv[6] * acc_a[i][6] * acc_b[i][6], 0.f);
        v1.w = fmaxf(tv[7] * acc_a[i][7] * acc_b[i][7], 0.f);
        *(float4*)(g_AA + (size_t)row * F + c0)     = v0;
        *(float4*)(g_AA + (size_t)row * F + c0 + 4) = v1;
    }
}

// ---------------------------------------------------------------------------
// Final layer: A = [g_AA | g_PS] (8192 x 256),
// out = relu(t3 * (A@W3a+b3a) * (A@W3b+b3b)). K=256 done in two 128-k phases.
// ---------------------------------------------------------------------------
extern "C" __global__ void __launch_bounds__(NTHREADS, 1)
eaw_atom2_kernel(const float* __restrict__ W3a, const float* __restrict__ b3a,
                 const float* __restrict__ W3b, const float* __restrict__ b3b,
                 const float* __restrict__ t3, float* __restrict__ out) {
    extern __shared__ float sm[];
    float* Wa_s = sm;
    float* Wb_s = sm + 16384;
    float* Xs   = sm + 32768;

    const int tid = threadIdx.x;
    const int rowBase = blockIdx.x * TM;
    const int tr = tid >> 4, tc = tid & 15;
    const int r0 = tr * 8, c0 = tc * 8;

    float acc_a[8][8], acc_b[8][8];
#pragma unroll
    for (int j = 0; j < 8; j++) {
        const float bav = b3a[c0 + j], bbv = b3b[c0 + j];
#pragma unroll
        for (int i = 0; i < 8; i++) { acc_a[i][j] = bav; acc_b[i][j] = bbv; }
    }

#pragma unroll 1
    for (int p = 0; p < 2; p++) {
        __syncthreads();
        const float* Xsrc = (p == 0 ? g_AA : g_PS) + (size_t)rowBase * F;
        const float4* wsa = (const float4*)(W3a + (size_t)p * 16384);
        const float4* wsb = (const float4*)(W3b + (size_t)p * 16384);
        for (int i = tid; i < 4096; i += NTHREADS) {
            ((float4*)Xs)[i]   = ((const float4*)Xsrc)[i];
            ((float4*)Wa_s)[i] = wsa[i];
            ((float4*)Wb_s)[i] = wsb[i];
        }
        __syncthreads();

        gemm_block(Wa_s, Wb_s, Xs, r0, c0, acc_a, acc_b);
    }

    float tv[8];
#pragma unroll
    for (int j = 0; j < 8; j++) tv[j] = t3[c0 + j];
#pragma unroll
    for (int i = 0; i < 8; i++) {
        const int row = rowBase + r0 + i;
        float4 v0, v1;
        v0.x = fmaxf(tv[0] * acc_a[i][0] * acc_b[i][0], 0.f);
        v0.y = fmaxf(tv[1] * acc_a[i][1] * acc_b[i][1], 0.f);
        v0.z = fmaxf(tv[2] * acc_a[i][2] * acc_b[i][2], 0.f);
        v0.w = fmaxf(tv[3] * acc_a[i][3] * acc_b[i][3], 0.f);
        v1.x = fmaxf(tv[4] * acc_a[i][4] * acc_b[i][4], 0.f);
        v1.y = fmaxf(tv[5] * acc_a[i][5] * acc_b[i][5], 0.f);
        v1.z = fmaxf(tv[6] * acc_a[i][6] * acc_b[i][6], 0.f);
        v1.w = fmaxf(tv[7] * acc_a[i][7] * acc_b[i][7], 0.f);
        *(float4*)(out + (size_t)row * F + c0)     = v0;
        *(float4*)(out + (size_t)row * F + c0 + 4) = v1;
    }
}

// ---------------------------------------------------------------------------
// Launch
// ---------------------------------------------------------------------------
extern "C" void kernel_launch(void* const* d_in, const int* in_sizes, int n_in,
                              void* d_out, int out_size) {
    const float* FA  = (const float*)d_in[0];
    const float* FP  = (const float*)d_in[1];
    const int*   sp  = (const int*)  d_in[2];
    const float* W1a = (const float*)d_in[3];
    const float* b1a = (const float*)d_in[4];
    const float* W1b = (const float*)d_in[5];
    const float* b1b = (const float*)d_in[6];
    const float* t1  = (const float*)d_in[7];
    const float* W2a = (const float*)d_in[8];
    const float* b2a = (const float*)d_in[9];
    const float* W2b = (const float*)d_in[10];
    const float* b2b = (const float*)d_in[11];
    const float* t2  = (const float*)d_in[12];
    const float* W3a = (const float*)d_in[13];
    const float* b3a = (const float*)d_in[14];
    const float* W3b = (const float*)d_in[15];
    const float* b3b = (const float*)d_in[16];
    const float* t3  = (const float*)d_in[17];
    float* out = (float*)d_out;

    const int nPairs    = in_sizes[1] / F;   // 524288
    const int nAtoms    = in_sizes[0] / F;   // 8192
    const int pairTiles = nPairs / TM;       // 4096
    const int atomTiles = nAtoms / TM;       // 64

    const size_t smem = 3 * 16384 * sizeof(float);  // 192 KB
    cudaFuncSetAttribute(eaw_pair_kernel,  cudaFuncAttributeMaxDynamicSharedMemorySize, (int)smem);
    cudaFuncSetAttribute(eaw_atom1_kernel, cudaFuncAttributeMaxDynamicSharedMemorySize, (int)smem);
    cudaFuncSetAttribute(eaw_atom2_kernel, cudaFuncAttributeMaxDynamicSharedMemorySize, (int)smem);

    int nsm = 148;
    cudaDeviceGetAttribute(&nsm, cudaDevAttrMultiProcessorCount, 0);

    eaw_zero_ps<<<(N_ATOMS * F / 4) / NTHREADS, NTHREADS>>>();
    eaw_pair_kernel<<<nsm, NTHREADS, smem>>>(FP, sp, W2a, b2a, W2b, b2b, t2, pairTiles);
    eaw_atom1_kernel<<<atomTiles, NTHREADS, smem>>>(FA, W1a, b1a, W1b, b1b, t1);
    eaw_atom2_kernel<<<atomTiles, NTHREADS, smem>>>(W3a, b3a, W3b, b3b, t3, out);
}

// round 3
// speedup vs baseline: 1.7597x; 1.7597x over previous
#include <cuda_runtime.h>
#include <cuda_bf16.h>
#include <cstdint>

#define F          128
#define NTHREADS   256
#define N_ATOMS    8192
#define TSTRIDE    272          // bf16 tile row stride in bytes (128*2 + 16 pad)
#define TILEB      34816        // 128 * TSTRIDE
#define STG_STRIDE 132          // fp32 staging row stride (words)

// ---------------------------------------------------------------------------
// Device-global scratch (no allocations allowed)
// ---------------------------------------------------------------------------
__device__ float g_PS[N_ATOMS * F];   // segment-summed pair activations
__device__ float g_AA[N_ATOMS * F];   // atom layer-1 output
// Prepped weights: bf16, B-orientation [n][k] (k contiguous), 272B row stride,
// hi/lo split. 16 tiles of 34816B:
//  0:W2a_hi 1:W2a_lo 2:W2b_hi 3:W2b_lo   4:W1a_hi 5:W1a_lo 6:W1b_hi 7:W1b_lo
//  8..11: W3 chunk0 (a_hi,a_lo,b_hi,b_lo)   12..15: W3 chunk1
__device__ __align__(16) unsigned char g_Wp[16 * TILEB];

// SMEM layout (dynamic): B tiles [0,139264), X_HI at 139264, X_LO at +34816.
// Epilogue staging (fp32 128x132 = 67584B) overlays the X region.
#define SM_B   0
#define SM_X   139264
#define SMEM_BYTES 208896

// ---------------------------------------------------------------------------
// PTX helpers (baseline ISA only: ldmatrix + mma.sync, sm_80+)
// ---------------------------------------------------------------------------
__device__ __forceinline__ uint32_t smem_u32(const void* p) {
    uint32_t a;
    asm("{ .reg .u64 t; cvta.to.shared.u64 t, %1; cvt.u32.u64 %0, t; }" : "=r"(a) : "l"(p));
    return a;
}
__device__ __forceinline__ void ldmx4(uint32_t* r, uint32_t addr) {
    asm volatile("ldmatrix.sync.aligned.m8n8.x4.shared.b16 {%0,%1,%2,%3}, [%4];"
                 : "=r"(r[0]), "=r"(r[1]), "=r"(r[2]), "=r"(r[3]) : "r"(addr));
}
__device__ __forceinline__ void mma16816(float* d, const uint32_t* a, uint32_t b0, uint32_t b1) {
    asm volatile(
        "mma.sync.aligned.m16n8k16.row.col.f32.bf16.bf16.f32 "
        "{%0,%1,%2,%3}, {%4,%5,%6,%7}, {%8,%9}, {%0,%1,%2,%3};"
        : "+f"(d[0]), "+f"(d[1]), "+f"(d[2]), "+f"(d[3])
        : "r"(a[0]), "r"(a[1]), "r"(a[2]), "r"(a[3]), "r"(b0), "r"(b1));
}
__device__ __forceinline__ void red_v4(float* addr, float a, float b, float c, float d) {
    asm volatile("red.global.add.v4.f32 [%0], {%1,%2,%3,%4};"
                 :: "l"(addr), "f"(a), "f"(b), "f"(c), "f"(d) : "memory");
}

// ---------------------------------------------------------------------------
// X tile store: fp32 float4 -> bf16 hi (X_HI) + bf16 lo (X_LO), [m][k] layout.
// i in [0,4096): m = i>>5, k4 = (i&31)*4.
// ---------------------------------------------------------------------------
union B2U { __nv_bfloat162 b; uint32_t u; };

__device__ __forceinline__ void x_store(char* sm, int i, float4 v) {
    const int m = i >> 5, k4 = (i & 31) << 2;
    char* p = sm + SM_X + m * TSTRIDE + k4 * 2;
    __nv_bfloat162 h0 = __float22bfloat162_rn(make_float2(v.x, v.y));
    __nv_bfloat162 h1 = __float22bfloat162_rn(make_float2(v.z, v.w));
    float2 f0 = __bfloat1622float2(h0), f1 = __bfloat1622float2(h1);
    __nv_bfloat162 l0 = __float22bfloat162_rn(make_float2(v.x - f0.x, v.y - f0.y));
    __nv_bfloat162 l1 = __float22bfloat162_rn(make_float2(v.z - f1.x, v.w - f1.y));
    B2U a, b, c, d; a.b = h0; b.b = h1; c.b = l0; d.b = l1;
    *(uint2*)p            = make_uint2(a.u, b.u);
    *(uint2*)(p + TILEB)  = make_uint2(c.u, d.u);
}

// ---------------------------------------------------------------------------
// One 128-K accumulation pass for both denses.
// Xb: X tile base (smem u32). Ba/Bb: weight tile bases. aTh/bTh: per-thread
// ldmatrix offsets. Warp patch: rows [mBase,mBase+64), cols [nBase,nBase+32).
// ---------------------------------------------------------------------------
__device__ __forceinline__ void kloop128(uint32_t Xb, uint32_t Ba, uint32_t Bb,
                                         uint32_t aTh, uint32_t bTh,
                                         int mBase, int nBase,
                                         float (&accA)[4][4][4], float (&accB)[4][4][4]) {
#pragma unroll
    for (int k0 = 0; k0 < 128; k0 += 16) {
        uint32_t a[4][4];
#pragma unroll
        for (int i = 0; i < 4; i++)
            ldmx4(a[i], Xb + (uint32_t)((mBase + 16 * i) * TSTRIDE) + (uint32_t)(k0 * 2) + aTh);
        uint32_t pa[2][4], pb[2][4];
#pragma unroll
        for (int j2 = 0; j2 < 2; j2++) {
            const uint32_t ro = (uint32_t)((nBase + 16 * j2) * TSTRIDE) + (uint32_t)(k0 * 2) + bTh;
            ldmx4(pa[j2], Ba + ro);
            ldmx4(pb[j2], Bb + ro);
        }
#pragma unroll
        for (int i = 0; i < 4; i++)
#pragma unroll
            for (int j = 0; j < 4; j++) {
                mma16816(accA[i][j], a[i], pa[j >> 1][(j & 1) * 2], pa[j >> 1][(j & 1) * 2 + 1]);
                mma16816(accB[i][j], a[i], pb[j >> 1][(j & 1) * 2], pb[j >> 1][(j & 1) * 2 + 1]);
            }
    }
}

// 3-term split pass: Xh*Wh + Xh*Wl + Xl*Wh
__device__ __forceinline__ void gemm3(uint32_t smb, uint32_t aTh, uint32_t bTh,
                                      int mBase, int nBase,
                                      float (&accA)[4][4][4], float (&accB)[4][4][4]) {
    const uint32_t XH = smb + SM_X, XL = XH + TILEB;
    const uint32_t BaH = smb, BaL = smb + TILEB, BbH = smb + 2 * TILEB, BbL = smb + 3 * TILEB;
    kloop128(XH, BaH, BbH, aTh, bTh, mBase, nBase, accA, accB);
    kloop128(XH, BaL, BbL, aTh, bTh, mBase, nBase, accA, accB);
    kloop128(XL, BaH, BbH, aTh, bTh, mBase, nBase, accA, accB);
}

// Epilogue: apply bias, t*ya*yb, relu; stage fp32 into X region.
__device__ __forceinline__ void stage_out(char* sm, int mBase, int nBase, int lane,
                                          const float (&accA)[4][4][4], const float (&accB)[4][4][4],
                                          const float (&bav)[4][2], const float (&bbv)[4][2],
                                          const float (&tv)[4][2]) {
    float* stg = (float*)(sm + SM_X);
    const int r0 = mBase + (lane >> 2);
#pragma unroll
    for (int i = 0; i < 4; i++) {
#pragma unroll
        for (int j = 0; j < 4; j++) {
            const int c = nBase + 8 * j + 2 * (lane & 3);
            float2 lo, hi;
            lo.x = fmaxf(tv[j][0] * (accA[i][j][0] + bav[j][0]) * (accB[i][j][0] + bbv[j][0]), 0.f);
            lo.y = fmaxf(tv[j][1] * (accA[i][j][1] + bav[j][1]) * (accB[i][j][1] + bbv[j][1]), 0.f);
            hi.x = fmaxf(tv[j][0] * (accA[i][j][2] + bav[j][0]) * (accB[i][j][2] + bbv[j][0]), 0.f);
            hi.y = fmaxf(tv[j][1] * (accA[i][j][3] + bav[j][1]) * (accB[i][j][3] + bbv[j][1]), 0.f);
            *(float2*)(stg + (r0 + 16 * i) * STG_STRIDE + c)     = lo;
            *(float2*)(stg + (r0 + 16 * i + 8) * STG_STRIDE + c) = hi;
        }
    }
}

// ---------------------------------------------------------------------------
// Zero the pair-sum accumulator
// ---------------------------------------------------------------------------
extern "C" __global__ void eaw_zero_ps() {
    const int i = blockIdx.x * blockDim.x + threadIdx.x;
    ((float4*)g_PS)[i] = make_float4(0.f, 0.f, 0.f, 0.f);
}

// ---------------------------------------------------------------------------
// Weight prep: transpose to [n][k] (272B stride), split hi/lo, store global.
// 512 blocks x 256 threads = 131072 elements.
// ---------------------------------------------------------------------------
extern "C" __global__ void eaw_prep(const float* __restrict__ W1a, const float* __restrict__ W1b,
                                    const float* __restrict__ W2a, const float* __restrict__ W2b,
                                    const float* __restrict__ W3a, const float* __restrict__ W3b) {
    const int e = blockIdx.x * blockDim.x + threadIdx.x;
    int mat, off;
    if (e < 65536) { mat = e >> 14; off = e & 16383; }
    else           { int e2 = e - 65536; mat = 4 + (e2 >> 15); off = e2 & 32767; }
    const float* W;
    switch (mat) {
        case 0: W = W2a; break; case 1: W = W2b; break;
        case 2: W = W1a; break; case 3: W = W1b; break;
        case 4: W = W3a; break; default: W = W3b; break;
    }
    const int n = off & 127, k = off >> 7;     // W[k][n] at W[off] (coalesced)
    const float v = W[off];
    const __nv_bfloat16 h  = __float2bfloat16(v);
    const __nv_bfloat16 lo = __float2bfloat16(v - __bfloat162float(h));
    const int p = k >> 7, kk = k & 127;
    int hiTile;
    switch (mat) {
        case 0: hiTile = 0; break; case 1: hiTile = 2; break;
        case 2: hiTile = 4; break; case 3: hiTile = 6; break;
        case 4: hiTile = 8 + 4 * p;  break;
        default: hiTile = 10 + 4 * p; break;
    }
    const size_t pos = (size_t)n * TSTRIDE + (size_t)kk * 2;
    *(__nv_bfloat16*)(g_Wp + (size_t)hiTile * TILEB + pos)       = h;
    *(__nv_bfloat16*)(g_Wp + (size_t)(hiTile + 1) * TILEB + pos) = lo;
}

// ---------------------------------------------------------------------------
// Pair branch (persistent): PA = relu(t2*(FP@W2a+b2a)*(FP@W2b+b2b));
// scatter-add into g_PS via red.global.add.v4.
// ---------------------------------------------------------------------------
extern "C" __global__ void __launch_bounds__(NTHREADS, 1)
eaw_pair_mm(const float* __restrict__ FP, const int* __restrict__ split,
            const float* __restrict__ b2a, const float* __restrict__ b2b,
            const float* __restrict__ t2, int nTiles) {
    extern __shared__ __align__(16) char sm[];
    const int tid = threadIdx.x;
    const uint32_t smb = smem_u32(sm);

    // weights: 4 tiles (139264B) linear copy
    {
        const uint4* src = (const uint4*)g_Wp;
        uint4* dst = (uint4*)(sm + SM_B);
        for (int i = tid; i < 8704; i += NTHREADS) dst[i] = src[i];
    }

    const int lane = tid & 31, w = tid >> 5;
    const int mBase = (w >> 2) * 64, nBase = (w & 3) * 32;
    const int q = lane >> 3, r = lane & 7;
    const uint32_t aTh = (uint32_t)((r + 8 * (q & 1)) * TSTRIDE + (q >> 1) * 16);
    const uint32_t bTh = (uint32_t)((r + 8 * (q >> 1)) * TSTRIDE + (q & 1) * 16);

    float bav[4][2], bbv[4][2], tv[4][2];
#pragma unroll
    for (int j = 0; j < 4; j++) {
        const int c = nBase + 8 * j + 2 * (lane & 3);
        bav[j][0] = b2a[c]; bav[j][1] = b2a[c + 1];
        bbv[j][0] = b2b[c]; bbv[j][1] = b2b[c + 1];
        tv[j][0]  = t2[c];  tv[j][1]  = t2[c + 1];
    }

    for (int tile = blockIdx.x; tile < nTiles; tile += gridDim.x) {
        // gmem loads first (long latency)
        float4 xv[16];
        {
            const float4* src = (const float4*)(FP + (size_t)tile * 16384);
#pragma unroll
            for (int qq = 0; qq < 16; qq++) xv[qq] = src[tid + qq * NTHREADS];
        }
        __syncthreads();   // staging reads of previous tile complete
#pragma unroll
        for (int qq = 0; qq < 16; qq++) x_store(sm, tid + qq * NTHREADS, xv[qq]);
        __syncthreads();   // X ready (and weights on first iter)

        float accA[4][4][4], accB[4][4][4];
#pragma unroll
        for (int i = 0; i < 4; i++)
#pragma unroll
            for (int j = 0; j < 4; j++)
#pragma unroll
                for (int kq = 0; kq < 4; kq++) { accA[i][j][kq] = 0.f; accB[i][j][kq] = 0.f; }

        gemm3(smb, aTh, bTh, mBase, nBase, accA, accB);

        __syncthreads();   // all warps done reading X before staging overwrite
        stage_out(sm, mBase, nBase, lane, accA, accB, bav, bbv, tv);
        __syncthreads();   // staging complete

        // scatter: 16 x red.v4 per thread
        const float* stg = (const float*)(sm + SM_X);
        const int* sp = split + tile * 128;
#pragma unroll
        for (int it = 0; it < 16; it++) {
            const int idx = tid + it * NTHREADS;
            const int row = idx >> 5, c4 = (idx & 31) << 2;
            const int atom = sp[row];
            const float4 v = *(const float4*)(stg + row * STG_STRIDE + c4);
            red_v4(g_PS + (size_t)atom * F + c4, v.x, v.y, v.z, v.w);
        }
    }
}

// ---------------------------------------------------------------------------
// Atom layer 1: g_AA = relu(t1*(FA@W1a+b1a)*(FA@W1b+b1b)). 64 CTAs.
// ---------------------------------------------------------------------------
extern "C" __global__ void __launch_bounds__(NTHREADS, 1)
eaw_atom1_mm(const float* __restrict__ FA,
             const float* __restrict__ b1a, const float* __restrict__ b1b,
             const float* __restrict__ t1) {
    extern __shared__ __align__(16) char sm[];
    const int tid = threadIdx.x;
    const uint32_t smb = smem_u32(sm);
    {
        const uint4* src = (const uint4*)(g_Wp + 4 * TILEB);
        uint4* dst = (uint4*)(sm + SM_B);
        for (int i = tid; i < 8704; i += NTHREADS) dst[i] = src[i];
    }
    const int lane = tid & 31, w = tid >> 5;
    const int mBase = (w >> 2) * 64, nBase = (w & 3) * 32;
    const int q = lane >> 3, r = lane & 7;
    const uint32_t aTh = (uint32_t)((r + 8 * (q & 1)) * TSTRIDE + (q >> 1) * 16);
    const uint32_t bTh = (uint32_t)((r + 8 * (q >> 1)) * TSTRIDE + (q & 1) * 16);

    float bav[4][2], bbv[4][2], tv[4][2];
#pragma unroll
    for (int j = 0; j < 4; j++) {
        const int c = nBase + 8 * j + 2 * (lane & 3);
        bav[j][0] = b1a[c]; bav[j][1] = b1a[c + 1];
        bbv[j][0] = b1b[c]; bbv[j][1] = b1b[c + 1];
        tv[j][0]  = t1[c];  tv[j][1]  = t1[c + 1];
    }

    {
        const float4* src = (const float4*)(FA + (size_t)blockIdx.x * 16384);
#pragma unroll
        for (int qq = 0; qq < 16; qq++) {
            const int i = tid + qq * NTHREADS;
            x_store(sm, i, src[i]);
        }
    }
    __syncthreads();

    float accA[4][4][4], accB[4][4][4];
#pragma unroll
    for (int i = 0; i < 4; i++)
#pragma unroll
        for (int j = 0; j < 4; j++)
#pragma unroll
            for (int kq = 0; kq < 4; kq++) { accA[i][j][kq] = 0.f; accB[i][j][kq] = 0.f; }

    gemm3(smb, aTh, bTh, mBase, nBase, accA, accB);

    __syncthreads();
    stage_out(sm, mBase, nBase, lane, accA, accB, bav, bbv, tv);
    __syncthreads();

    const float* stg = (const float*)(sm + SM_X);
    float* dst = g_AA + (size_t)blockIdx.x * 16384;
#pragma unroll
    for (int it = 0; it < 16; it++) {
        const int idx = tid + it * NTHREADS;
        const int row = idx >> 5, c4 = (idx & 31) << 2;
        *(float4*)(dst + row * F + c4) = *(const float4*)(stg + row * STG_STRIDE + c4);
    }
}

// ---------------------------------------------------------------------------
// Final layer (K=256 via two phases): out = relu(t3*([AA|PS]@W3a+b3a)*(...b)).
// ---------------------------------------------------------------------------
extern "C" __global__ void __launch_bounds__(NTHREADS, 1)
eaw_atom2_mm(const float* __restrict__ b3a, const float* __restrict__ b3b,
             const float* __restrict__ t3, float* __restrict__ out) {
    extern __shared__ __align__(16) char sm[];
    const int tid = threadIdx.x;
    const uint32_t smb = smem_u32(sm);
    const int lane = tid & 31, w = tid >> 5;
    const int mBase = (w >> 2) * 64, nBase = (w & 3) * 32;
    const int q = lane >> 3, r = lane & 7;
    const uint32_t aTh = (uint32_t)((r + 8 * (q & 1)) * TSTRIDE + (q >> 1) * 16);
    const uint32_t bTh = (uint32_t)((r + 8 * (q >> 1)) * TSTRIDE + (q & 1) * 16);

    float bav[4][2], bbv[4][2], tv[4][2];
#pragma unroll
    for (int j = 0; j < 4; j++) {
        const int c = nBase + 8 * j + 2 * (lane & 3);
        bav[j][0] = b3a[c]; bav[j][1] = b3a[c + 1];
        bbv[j][0] = b3b[c]; bbv[j][1] = b3b[c + 1];
        tv[j][0]  = t3[c];  tv[j][1]  = t3[c + 1];
    }

    float accA[4][4][4], accB[4][4][4];
#pragma unroll
    for (int i = 0; i < 4; i++)
#pragma unroll
        for (int j = 0; j < 4; j++)
#pragma unroll
            for (int kq = 0; kq < 4; kq++) { accA[i][j][kq] = 0.f; accB[i][j][kq] = 0.f; }

#pragma unroll 1
    for (int p = 0; p < 2; p++) {
        __syncthreads();  // previous phase's smem reads complete
        {
            const uint4* src = (const uint4*)(g_Wp + (size_t)(8 + 4 * p) * TILEB);
            uint4* dst = (uint4*)(sm + SM_B);
            for (int i = tid; i < 8704; i += NTHREADS) dst[i] = src[i];
        }
        {
            const float* Xsrc = (p == 0 ? g_AA : g_PS) + (size_t)blockIdx.x * 16384;
            const float4* src = (const float4*)Xsrc;
#pragma unroll
            for (int qq = 0; qq < 16; qq++) {
                const int i = tid + qq * NTHREADS;
                x_store(sm, i, src[i]);
            }
        }
        __syncthreads();
        gemm3(smb, aTh, bTh, mBase, nBase, accA, accB);
    }

    __syncthreads();
    stage_out(sm, mBase, nBase, lane, accA, accB, bav, bbv, tv);
    __syncthreads();

    const float* stg = (const float*)(sm + SM_X);
    float* dst = out + (size_t)blockIdx.x * 16384;
#pragma unroll
    for (int it = 0; it < 16; it++) {
        const int idx = tid + it * NTHREADS;
        const int row = idx >> 5, c4 = (idx & 31) << 2;
        *(float4*)(dst + row * F + c4) = *(const float4*)(stg + row * STG_STRIDE + c4);
    }
}

// ---------------------------------------------------------------------------
// Launch
// ---------------------------------------------------------------------------
extern "C" void kernel_launch(void* const* d_in, const int* in_sizes, int n_in,
                              void* d_out, int out_size) {
    const float* FA  = (const float*)d_in[0];
    const float* FP  = (const float*)d_in[1];
    const int*   sp  = (const int*)  d_in[2];
    const float* W1a = (const float*)d_in[3];
    const float* b1a = (const float*)d_in[4];
    const float* W1b = (const float*)d_in[5];
    const float* b1b = (const float*)d_in[6];
    const float* t1  = (const float*)d_in[7];
    const float* W2a = (const float*)d_in[8];
    const float* b2a = (const float*)d_in[9];
    const float* W2b = (const float*)d_in[10];
    const float* b2b = (const float*)d_in[11];
    const float* t2  = (const float*)d_in[12];
    const float* W3a = (const float*)d_in[13];
    const float* b3a = (const float*)d_in[14];
    const float* W3b = (const float*)d_in[15];
    const float* b3b = (const float*)d_in[16];
    const float* t3  = (const float*)d_in[17];
    float* out = (float*)d_out;

    const int nPairs    = in_sizes[1] / F;   // 524288
    const int pairTiles = nPairs / 128;      // 4096

    cudaFuncSetAttribute(eaw_pair_mm,  cudaFuncAttributeMaxDynamicSharedMemorySize, SMEM_BYTES);
    cudaFuncSetAttribute(eaw_atom1_mm, cudaFuncAttributeMaxDynamicSharedMemorySize, SMEM_BYTES);
    cudaFuncSetAttribute(eaw_atom2_mm, cudaFuncAttributeMaxDynamicSharedMemorySize, SMEM_BYTES);

    int nsm = 148;
    cudaDeviceGetAttribute(&nsm, cudaDevAttrMultiProcessorCount, 0);

    eaw_zero_ps<<<(N_ATOMS * F / 4) / NTHREADS, NTHREADS>>>();
    eaw_prep<<<512, NTHREADS>>>(W1a, W1b, W2a, W2b, W3a, W3b);
    eaw_pair_mm<<<nsm, NTHREADS, SMEM_BYTES>>>(FP, sp, b2a, b2b, t2, pairTiles);
    eaw_atom1_mm<<<64, NTHREADS, SMEM_BYTES>>>(FA, b1a, b1b, t1);
    eaw_atom2_mm<<<64, NTHREADS, SMEM_BYTES>>>(b3a, b3b, t3, out);
}

// round 4
// speedup vs baseline: 2.1970x; 1.2485x over previous
#include <cuda_runtime.h>
#include <cuda_bf16.h>
#include <cstdint>

#define F          128
#define THREADS    512
#define N_ATOMS    8192
#define TSTRIDE    272          // bf16 tile row stride in bytes (128*2 + 16 pad)
#define TILEB      34816        // 128 * TSTRIDE

// ---------------------------------------------------------------------------
// Device-global scratch (no allocations allowed)
// ---------------------------------------------------------------------------
__device__ float g_PS[N_ATOMS * F];   // segment-summed pair activations
__device__ float g_AA[N_ATOMS * F];   // atom layer-1 output
// Prepped weights: bf16, B-orientation [n][k] (k contiguous), 272B row stride,
// hi/lo split. 16 tiles of 34816B:
//  0:W2a_hi 1:W2a_lo 2:W2b_hi 3:W2b_lo   4:W1a_hi 5:W1a_lo 6:W1b_hi 7:W1b_lo
//  8..11: W3 chunk0 (a_hi,a_lo,b_hi,b_lo)   12..15: W3 chunk1
__device__ __align__(16) unsigned char g_Wp[16 * TILEB];

// SMEM: weight tiles [0,139264), X_HI at 139264, X_LO +34816, bias at 208896.
#define SM_X     139264
#define SM_BIAS  208896
#define SMEM_BYTES 210432

// ---------------------------------------------------------------------------
// PTX helpers (baseline ISA: ldmatrix + mma.sync + red, sm_90-safe)
// ---------------------------------------------------------------------------
__device__ __forceinline__ uint32_t smem_u32(const void* p) {
    uint32_t a;
    asm("{ .reg .u64 t; cvta.to.shared.u64 t, %1; cvt.u32.u64 %0, t; }" : "=r"(a) : "l"(p));
    return a;
}
__device__ __forceinline__ void ldmx4(uint32_t* r, uint32_t addr) {
    asm volatile("ldmatrix.sync.aligned.m8n8.x4.shared.b16 {%0,%1,%2,%3}, [%4];"
                 : "=r"(r[0]), "=r"(r[1]), "=r"(r[2]), "=r"(r[3]) : "r"(addr));
}
__device__ __forceinline__ void mma16816(float* d, const uint32_t* a, uint32_t b0, uint32_t b1) {
    asm volatile(
        "mma.sync.aligned.m16n8k16.row.col.f32.bf16.bf16.f32 "
        "{%0,%1,%2,%3}, {%4,%5,%6,%7}, {%8,%9}, {%0,%1,%2,%3};"
        : "+f"(d[0]), "+f"(d[1]), "+f"(d[2]), "+f"(d[3])
        : "r"(a[0]), "r"(a[1]), "r"(a[2]), "r"(a[3]), "r"(b0), "r"(b1));
}
__device__ __forceinline__ void red_v2(float* addr, float a, float b) {
    asm volatile("red.global.add.v2.f32 [%0], {%1,%2};"
                 :: "l"(addr), "f"(a), "f"(b) : "memory");
}

// ---------------------------------------------------------------------------
// X tile store: fp32 float4 -> bf16 hi (X_HI) + lo (X_LO), [m][k], 272B stride.
// i in [0,4096): m = i>>5, k4 = (i&31)*4.
// ---------------------------------------------------------------------------
union B2U { __nv_bfloat162 b; uint32_t u; };

__device__ __forceinline__ void x_store(char* sm, int i, float4 v) {
    const int m = i >> 5, k4 = (i & 31) << 2;
    char* p = sm + SM_X + m * TSTRIDE + k4 * 2;
    __nv_bfloat162 h0 = __float22bfloat162_rn(make_float2(v.x, v.y));
    __nv_bfloat162 h1 = __float22bfloat162_rn(make_float2(v.z, v.w));
    float2 f0 = __bfloat1622float2(h0), f1 = __bfloat1622float2(h1);
    __nv_bfloat162 l0 = __float22bfloat162_rn(make_float2(v.x - f0.x, v.y - f0.y));
    __nv_bfloat162 l1 = __float22bfloat162_rn(make_float2(v.z - f1.x, v.w - f1.y));
    B2U a, b, c, d; a.b = h0; b.b = h1; c.b = l0; d.b = l1;
    *(uint2*)p           = make_uint2(a.u, b.u);
    *(uint2*)(p + TILEB) = make_uint2(c.u, d.u);
}

__device__ __forceinline__ void x_tile_load(char* sm, const float* __restrict__ src, int tid) {
    const float4* s4 = (const float4*)src;
#pragma unroll
    for (int h = 0; h < 2; h++) {
        float4 xv[4];
#pragma unroll
        for (int q = 0; q < 4; q++) xv[q] = s4[tid + (4 * h + q) * THREADS];
#pragma unroll
        for (int q = 0; q < 4; q++) x_store(sm, tid + (4 * h + q) * THREADS, xv[q]);
    }
}

// ---------------------------------------------------------------------------
// Fused 3-term GEMM for both denses. Warp patch: 32 rows x 32 cols.
// Pass 1 (XH): each A-fragment hits all 4 weight tiles (Wh+Wl for both denses).
// Pass 2 (XL): A-lo hits the hi weight tiles only.
// acc layout: acc[i][j][4], i in {0,1} (16-row blocks), j in {0..3} (8-col).
// ---------------------------------------------------------------------------
__device__ __forceinline__ void gemm3(uint32_t smb, uint32_t aTh, uint32_t bTh,
                                      int mBase, int nBase,
                                      float (&accA)[2][4][4], float (&accB)[2][4][4]) {
    const uint32_t XH = smb + SM_X, XL = XH + TILEB;
    const uint32_t a0row = (uint32_t)(mBase * TSTRIDE) + aTh;
    const uint32_t a1row = a0row + (uint32_t)(16 * TSTRIDE);

    // ---- pass 1: Xh x {WaH, WaL, WbH, WbL} ----
#pragma unroll
    for (int k0 = 0; k0 < 128; k0 += 16) {
        const uint32_t ko = (uint32_t)(k0 * 2);
        uint32_t a0[4], a1[4];
        ldmx4(a0, XH + a0row + ko);
        ldmx4(a1, XH + a1row + ko);
#pragma unroll
        for (int j2 = 0; j2 < 2; j2++) {
            const uint32_t ro = (uint32_t)((nBase + 16 * j2) * TSTRIDE) + ko + bTh;
            uint32_t paH[4], paL[4], pbH[4], pbL[4];
            ldmx4(paH, smb + ro);
            ldmx4(paL, smb + TILEB + ro);
            ldmx4(pbH, smb + 2 * TILEB + ro);
            ldmx4(pbL, smb + 3 * TILEB + ro);
#pragma unroll
            for (int jj = 0; jj < 2; jj++) {
                const int j = 2 * j2 + jj;
                mma16816(accA[0][j], a0, paH[2 * jj], paH[2 * jj + 1]);
                mma16816(accA[1][j], a1, paH[2 * jj], paH[2 * jj + 1]);
                mma16816(accA[0][j], a0, paL[2 * jj], paL[2 * jj + 1]);
                mma16816(accA[1][j], a1, paL[2 * jj], paL[2 * jj + 1]);
                mma16816(accB[0][j], a0, pbH[2 * jj], pbH[2 * jj + 1]);
                mma16816(accB[1][j], a1, pbH[2 * jj], pbH[2 * jj + 1]);
                mma16816(accB[0][j], a0, pbL[2 * jj], pbL[2 * jj + 1]);
                mma16816(accB[1][j], a1, pbL[2 * jj], pbL[2 * jj + 1]);
            }
        }
    }
    // ---- pass 2: Xl x {WaH, WbH} ----
#pragma unroll
    for (int k0 = 0; k0 < 128; k0 += 16) {
        const uint32_t ko = (uint32_t)(k0 * 2);
        uint32_t a0[4], a1[4];
        ldmx4(a0, XL + a0row + ko);
        ldmx4(a1, XL + a1row + ko);
#pragma unroll
        for (int j2 = 0; j2 < 2; j2++) {
            const uint32_t ro = (uint32_t)((nBase + 16 * j2) * TSTRIDE) + ko + bTh;
            uint32_t paH[4], pbH[4];
            ldmx4(paH, smb + ro);
            ldmx4(pbH, smb + 2 * TILEB + ro);
#pragma unroll
            for (int jj = 0; jj < 2; jj++) {
                const int j = 2 * j2 + jj;
                mma16816(accA[0][j], a0, paH[2 * jj], paH[2 * jj + 1]);
                mma16816(accA[1][j], a1, paH[2 * jj], paH[2 * jj + 1]);
                mma16816(accB[0][j], a0, pbH[2 * jj], pbH[2 * jj + 1]);
                mma16816(accB[1][j], a1, pbH[2 * jj], pbH[2 * jj + 1]);
            }
        }
    }
}

// ---------------------------------------------------------------------------
// Weight prep (+ zero g_PS): transpose to [n][k] (272B stride), split hi/lo.
// 512 blocks x 256 threads = 131072 threads.
// ---------------------------------------------------------------------------
extern "C" __global__ void eaw_prep(const float* __restrict__ W1a, const float* __restrict__ W1b,
                                    const float* __restrict__ W2a, const float* __restrict__ W2b,
                                    const float* __restrict__ W3a, const float* __restrict__ W3b) {
    const int e = blockIdx.x * blockDim.x + threadIdx.x;
    // zero pair accumulator (2 float4 per thread)
    ((float4*)g_PS)[e]          = make_float4(0.f, 0.f, 0.f, 0.f);
    ((float4*)g_PS)[e + 131072] = make_float4(0.f, 0.f, 0.f, 0.f);

    int mat, off;
    if (e < 65536) { mat = e >> 14; off = e & 16383; }
    else           { int e2 = e - 65536; mat = 4 + (e2 >> 15); off = e2 & 32767; }
    const float* W;
    switch (mat) {
        case 0: W = W2a; break; case 1: W = W2b; break;
        case 2: W = W1a; break; case 3: W = W1b; break;
        case 4: W = W3a; break; default: W = W3b; break;
    }
    const int n = off & 127, k = off >> 7;     // W[k][n] at W[off] (coalesced)
    const float v = W[off];
    const __nv_bfloat16 h  = __float2bfloat16(v);
    const __nv_bfloat16 lo = __float2bfloat16(v - __bfloat162float(h));
    const int p = k >> 7, kk = k & 127;
    int hiTile;
    switch (mat) {
        case 0: hiTile = 0; break; case 1: hiTile = 2; break;
        case 2: hiTile = 4; break; case 3: hiTile = 6; break;
        case 4: hiTile = 8 + 4 * p;  break;
        default: hiTile = 10 + 4 * p; break;
    }
    const size_t pos = (size_t)n * TSTRIDE + (size_t)kk * 2;
    *(__nv_bfloat16*)(g_Wp + (size_t)hiTile * TILEB + pos)       = h;
    *(__nv_bfloat16*)(g_Wp + (size_t)(hiTile + 1) * TILEB + pos) = lo;
}

// ---------------------------------------------------------------------------
// Pair branch (persistent): relu(t2*(FP@W2a+b2a)*(FP@W2b+b2b)) scatter-added
// into g_PS straight from registers via red.global.add.v2.
// ---------------------------------------------------------------------------
extern "C" __global__ void __launch_bounds__(THREADS, 1)
eaw_pair_mm(const float* __restrict__ FP, const int* __restrict__ split,
            const float* __restrict__ b2a, const float* __restrict__ b2b,
            const float* __restrict__ t2, int nTiles) {
    extern __shared__ __align__(16) char sm[];
    const int tid = threadIdx.x;
    const uint32_t smb = smem_u32(sm);

    {   // weights: 4 tiles, 139264B linear copy (L2-broadcast across CTAs)
        const uint4* src = (const uint4*)g_Wp;
        uint4* dst = (uint4*)sm;
        for (int i = tid; i < 8704; i += THREADS) dst[i] = src[i];
    }
    if (tid < 128) {
        ((float*)(sm + SM_BIAS))[tid]       = b2a[tid];
        ((float*)(sm + SM_BIAS))[128 + tid] = b2b[tid];
        ((float*)(sm + SM_BIAS))[256 + tid] = t2[tid];
    }

    const int lane = tid & 31, w = tid >> 5;
    const int mBase = (w >> 2) * 32, nBase = (w & 3) * 32;
    const int q = lane >> 3, r = lane & 7;
    const uint32_t aTh = (uint32_t)((r + 8 * (q & 1)) * TSTRIDE + (q >> 1) * 16);
    const uint32_t bTh = (uint32_t)((r + 8 * (q >> 1)) * TSTRIDE + (q & 1) * 16);
    const float* biasA = (const float*)(sm + SM_BIAS);
    const float* biasB = biasA + 128;
    const float* tvv   = biasA + 256;

    __syncthreads();

    for (int tile = blockIdx.x; tile < nTiles; tile += gridDim.x) {
        x_tile_load(sm, FP + (size_t)tile * 16384, tid);
        __syncthreads();                 // X (and, first iter, weights) ready

        float accA[2][4][4], accB[2][4][4];
#pragma unroll
        for (int i = 0; i < 2; i++)
#pragma unroll
            for (int j = 0; j < 4; j++)
#pragma unroll
                for (int kq = 0; kq < 4; kq++) { accA[i][j][kq] = 0.f; accB[i][j][kq] = 0.f; }

        gemm3(smb, aTh, bTh, mBase, nBase, accA, accB);

        // register-direct epilogue: relu(t*(ya)*(yb)), red.v2 scatter
        const int* sp = split + tile * 128;
#pragma unroll
        for (int i = 0; i < 2; i++) {
#pragma unroll
            for (int sub = 0; sub < 2; sub++) {
                const int row = mBase + 16 * i + (lane >> 2) + 8 * sub;
                const int atom = sp[row];
                float* dst = g_PS + (size_t)atom * F;
#pragma unroll
                for (int j = 0; j < 4; j++) {
                    const int c = nBase + 8 * j + 2 * (lane & 3);
                    const float v0 = fmaxf(tvv[c]     * (accA[i][j][2 * sub]     + biasA[c])     * (accB[i][j][2 * sub]     + biasB[c]),     0.f);
                    const float v1 = fmaxf(tvv[c + 1] * (accA[i][j][2 * sub + 1] + biasA[c + 1]) * (accB[i][j][2 * sub + 1] + biasB[c + 1]), 0.f);
                    red_v2(dst + c, v0, v1);
                }
            }
        }
        __syncthreads();                 // all gemm reads done before next x_store
    }
}

// ---------------------------------------------------------------------------
// Atom layer 1: g_AA = relu(t1*(FA@W1a+b1a)*(FA@W1b+b1b)). 64 CTAs.
// ---------------------------------------------------------------------------
extern "C" __global__ void __launch_bounds__(THREADS, 1)
eaw_atom1_mm(const float* __restrict__ FA,
             const float* __restrict__ b1a, const float* __restrict__ b1b,
             const float* __restrict__ t1) {
    extern __shared__ __align__(16) char sm[];
    const int tid = threadIdx.x;
    const uint32_t smb = smem_u32(sm);
    {
        const uint4* src = (const uint4*)(g_Wp + 4 * TILEB);
        uint4* dst = (uint4*)sm;
        for (int i = tid; i < 8704; i += THREADS) dst[i] = src[i];
    }
    if (tid < 128) {
        ((float*)(sm + SM_BIAS))[tid]       = b1a[tid];
        ((float*)(sm + SM_BIAS))[128 + tid] = b1b[tid];
        ((float*)(sm + SM_BIAS))[256 + tid] = t1[tid];
    }
    const int lane = tid & 31, w = tid >> 5;
    const int mBase = (w >> 2) * 32, nBase = (w & 3) * 32;
    const int q = lane >> 3, r = lane & 7;
    const uint32_t aTh = (uint32_t)((r + 8 * (q & 1)) * TSTRIDE + (q >> 1) * 16);
    const uint32_t bTh = (uint32_t)((r + 8 * (q >> 1)) * TSTRIDE + (q & 1) * 16);
    const float* biasA = (const float*)(sm + SM_BIAS);
    const float* biasB = biasA + 128;
    const float* tvv   = biasA + 256;

    x_tile_load(sm, FA + (size_t)blockIdx.x * 16384, tid);
    __syncthreads();

    float accA[2][4][4], accB[2][4][4];
#pragma unroll
    for (int i = 0; i < 2; i++)
#pragma unroll
        for (int j = 0; j < 4; j++)
#pragma unroll
            for (int kq = 0; kq < 4; kq++) { accA[i][j][kq] = 0.f; accB[i][j][kq] = 0.f; }

    gemm3(smb, aTh, bTh, mBase, nBase, accA, accB);

    float* base = g_AA + (size_t)blockIdx.x * 16384;
#pragma unroll
    for (int i = 0; i < 2; i++) {
#pragma unroll
        for (int sub = 0; sub < 2; sub++) {
            const int row = mBase + 16 * i + (lane >> 2) + 8 * sub;
#pragma unroll
            for (int j = 0; j < 4; j++) {
                const int c = nBase + 8 * j + 2 * (lane & 3);
                float2 v;
                v.x = fmaxf(tvv[c]     * (accA[i][j][2 * sub]     + biasA[c])     * (accB[i][j][2 * sub]     + biasB[c]),     0.f);
                v.y = fmaxf(tvv[c + 1] * (accA[i][j][2 * sub + 1] + biasA[c + 1]) * (accB[i][j][2 * sub + 1] + biasB[c + 1]), 0.f);
                *(float2*)(base + (size_t)row * F + c) = v;
            }
        }
    }
}

// ---------------------------------------------------------------------------
// Final layer (K=256 via two phases): out = relu(t3*([AA|PS]@W3a+b3a)*(...b)).
// ---------------------------------------------------------------------------
extern "C" __global__ void __launch_bounds__(THREADS, 1)
eaw_atom2_mm(const float* __restrict__ b3a, const float* __restrict__ b3b,
             const float* __restrict__ t3, float* __restrict__ out) {
    extern __shared__ __align__(16) char sm[];
    const int tid = threadIdx.x;
    const uint32_t smb = smem_u32(sm);
    if (tid < 128) {
        ((float*)(sm + SM_BIAS))[tid]       = b3a[tid];
        ((float*)(sm + SM_BIAS))[128 + tid] = b3b[tid];
        ((float*)(sm + SM_BIAS))[256 + tid] = t3[tid];
    }
    const int lane = tid & 31, w = tid >> 5;
    const int mBase = (w >> 2) * 32, nBase = (w & 3) * 32;
    const int q = lane >> 3, r = lane & 7;
    const uint32_t aTh = (uint32_t)((r + 8 * (q & 1)) * TSTRIDE + (q >> 1) * 16);
    const uint32_t bTh = (uint32_t)((r + 8 * (q >> 1)) * TSTRIDE + (q & 1) * 16);
    const float* biasA = (const float*)(sm + SM_BIAS);
    const float* biasB = biasA + 128;
    const float* tvv   = biasA + 256;

    float accA[2][4][4], accB[2][4][4];
#pragma unroll
    for (int i = 0; i < 2; i++)
#pragma unroll
        for (int j = 0; j < 4; j++)
#pragma unroll
            for (int kq = 0; kq < 4; kq++) { accA[i][j][kq] = 0.f; accB[i][j][kq] = 0.f; }

#pragma unroll 1
    for (int p = 0; p < 2; p++) {
        if (p) __syncthreads();          // previous phase's smem reads complete
        {
            const uint4* src = (const uint4*)(g_Wp + (size_t)(8 + 4 * p) * TILEB);
            uint4* dst = (uint4*)sm;
            for (int i = tid; i < 8704; i += THREADS) dst[i] = src[i];
        }
        x_tile_load(sm, (p == 0 ? g_AA : g_PS) + (size_t)blockIdx.x * 16384, tid);
        __syncthreads();
        gemm3(smb, aTh, bTh, mBase, nBase, accA, accB);
    }

    float* base = out + (size_t)blockIdx.x * 16384;
#pragma unroll
    for (int i = 0; i < 2; i++) {
#pragma unroll
        for (int sub = 0; sub < 2; sub++) {
            const int row = mBase + 16 * i + (lane >> 2) + 8 * sub;
#pragma unroll
            for (int j = 0; j < 4; j++) {
                const int c = nBase + 8 * j + 2 * (lane & 3);
                float2 v;
                v.x = fmaxf(tvv[c]     * (accA[i][j][2 * sub]     + biasA[c])     * (accB[i][j][2 * sub]     + biasB[c]),     0.f);
                v.y = fmaxf(tvv[c + 1] * (accA[i][j][2 * sub + 1] + biasA[c + 1]) * (accB[i][j][2 * sub + 1] + biasB[c + 1]), 0.f);
                *(float2*)(base + (size_t)row * F + c) = v;
            }
        }
    }
}

// ---------------------------------------------------------------------------
// Launch
// ---------------------------------------------------------------------------
extern "C" void kernel_launch(void* const* d_in, const int* in_sizes, int n_in,
                              void* d_out, int out_size) {
    const float* FA  = (const float*)d_in[0];
    const float* FP  = (const float*)d_in[1];
    const int*   sp  = (const int*)  d_in[2];
    const float* W1a = (const float*)d_in[3];
    const float* b1a = (const float*)d_in[4];
    const float* W1b = (const float*)d_in[5];
    const float* b1b = (const float*)d_in[6];
    const float* t1  = (const float*)d_in[7];
    const float* W2a = (const float*)d_in[8];
    const float* b2a = (const float*)d_in[9];
    const float* W2b = (const float*)d_in[10];
    const float* b2b = (const float*)d_in[11];
    const float* t2  = (const float*)d_in[12];
    const float* W3a = (const float*)d_in[13];
    const float* b3a = (const float*)d_in[14];
    const float* W3b = (const float*)d_in[15];
    const float* b3b = (const float*)d_in[16];
    const float* t3  = (const float*)d_in[17];
    float* out = (float*)d_out;

    const int nPairs    = in_sizes[1] / F;   // 524288
    const int pairTiles = nPairs / 128;      // 4096

    cudaFuncSetAttribute(eaw_pair_mm,  cudaFuncAttributeMaxDynamicSharedMemorySize, SMEM_BYTES);
    cudaFuncSetAttribute(eaw_atom1_mm, cudaFuncAttributeMaxDynamicSharedMemorySize, SMEM_BYTES);
    cudaFuncSetAttribute(eaw_atom2_mm, cudaFuncAttributeMaxDynamicSharedMemorySize, SMEM_BYTES);

    int nsm = 148;
    cudaDeviceGetAttribute(&nsm, cudaDevAttrMultiProcessorCount, 0);

    eaw_prep<<<512, 256>>>(W1a, W1b, W2a, W2b, W3a, W3b);
    eaw_pair_mm<<<nsm, THREADS, SMEM_BYTES>>>(FP, sp, b2a, b2b, t2, pairTiles);
    eaw_atom1_mm<<<64, THREADS, SMEM_BYTES>>>(FA, b1a, b1b, t1);
    eaw_atom2_mm<<<64, THREADS, SMEM_BYTES>>>(b3a, b3b, t3, out);
}

// round 6
// speedup vs baseline: 2.6654x; 1.2132x over previous
#include <cuda_runtime.h>
#include <cuda_bf16.h>
#include <cstdint>

#define F        128
#define THREADS  256
#define N_ATOMS  8192
#define TILE_M   64
#define TILEB    32768        // weight tile: 128 rows * 256B (bf16, swizzled)

// ---------------------------------------------------------------------------
// Device-global scratch (no allocations allowed)
// ---------------------------------------------------------------------------
__device__ float g_PS[N_ATOMS * F];   // segment-summed pair activations
__device__ float g_AA[N_ATOMS * F];   // atom layer-1 output
// Prepped weights: bf16, B-orientation [n][k], 256B rows, XOR-swizzled chunks,
// hi/lo split. 16 tiles of 32768B:
//  0:W2aH 1:W2aL 2:W2bH 3:W2bL  4:W1aH 5:W1aL 6:W1bH 7:W1bL
//  8..11: W3 chunk0 (aH,aL,bH,bL)  12..15: W3 chunk1
__device__ __align__(256) unsigned char g_Wp[16 * TILEB];

// SMEM map (dynamic, base 1024-aligned):
//  [0,131072)        4 weight tiles (aH, aL, bH, bL)
//  [131072,147456)   X hi bf16 (64 rows x 256B)
//  [147456,163840)   X lo bf16
//  [163840,196608)   fp32 stage (64 rows x 128 fp32 = 32KB)
//  [196608,198144)   bias: ba[128], bb[128], t[128]
#define SM_XH    131072
#define SM_XL    147456
#define SM_STG   163840
#define SM_BIAS  196608
#define SMEM_BYTES 198144

// ---------------------------------------------------------------------------
// PTX helpers (baseline ISA: ldmatrix, mma.sync, cp.async, red)
// ---------------------------------------------------------------------------
__device__ __forceinline__ uint32_t smem_u32(const void* p) {
    uint32_t a;
    asm("{ .reg .u64 t; cvta.to.shared.u64 t, %1; cvt.u32.u64 %0, t; }" : "=r"(a) : "l"(p));
    return a;
}
__device__ __forceinline__ void ldmx4(uint32_t* r, uint32_t addr) {
    asm volatile("ldmatrix.sync.aligned.m8n8.x4.shared.b16 {%0,%1,%2,%3}, [%4];"
                 : "=r"(r[0]), "=r"(r[1]), "=r"(r[2]), "=r"(r[3]) : "r"(addr));
}
__device__ __forceinline__ void mma16816(float* d, const uint32_t* a, uint32_t b0, uint32_t b1) {
    asm volatile(
        "mma.sync.aligned.m16n8k16.row.col.f32.bf16.bf16.f32 "
        "{%0,%1,%2,%3}, {%4,%5,%6,%7}, {%8,%9}, {%0,%1,%2,%3};"
        : "+f"(d[0]), "+f"(d[1]), "+f"(d[2]), "+f"(d[3])
        : "r"(a[0]), "r"(a[1]), "r"(a[2]), "r"(a[3]), "r"(b0), "r"(b1));
}
__device__ __forceinline__ void red_v2(float* addr, float a, float b) {
    asm volatile("red.global.add.v2.f32 [%0], {%1,%2};"
                 :: "l"(addr), "f"(a), "f"(b) : "memory");
}
__device__ __forceinline__ void cpa16(uint32_t saddr, const void* g) {
    asm volatile("cp.async.cg.shared.global [%0], [%1], 16;" :: "r"(saddr), "l"(g));
}
__device__ __forceinline__ void cpa_commit() {
    asm volatile("cp.async.commit_group;" ::: "memory");
}
__device__ __forceinline__ void cpa_wait0() {
    asm volatile("cp.async.wait_group 0;" ::: "memory");
}

// ---------------------------------------------------------------------------
// X element store: fp32 float4 -> bf16 hi/lo at swizzled (row m, k4).
// i = float4 index in [0,2048): m = i>>5 in [0,64), k4 = (i&31)*4.
// Layout: 256B rows; 16B chunk c holds k in [8c,8c+8) at chunk (c ^ (m&7)).
// ---------------------------------------------------------------------------
union B2U { __nv_bfloat162 b; uint32_t u; };

__device__ __forceinline__ void x_store(char* sm, int i, float4 v) {
    const int m = i >> 5, k4 = (i & 31) << 2;
    const uint32_t sw = (uint32_t)(m << 8) + ((uint32_t)(((k4 >> 3) ^ (m & 7))) << 4)
                      + ((uint32_t)((k4 >> 2) & 1) << 3);
    __nv_bfloat162 h0 = __float22bfloat162_rn(make_float2(v.x, v.y));
    __nv_bfloat162 h1 = __float22bfloat162_rn(make_float2(v.z, v.w));
    float2 f0 = __bfloat1622float2(h0), f1 = __bfloat1622float2(h1);
    __nv_bfloat162 l0 = __float22bfloat162_rn(make_float2(v.x - f0.x, v.y - f0.y));
    __nv_bfloat162 l1 = __float22bfloat162_rn(make_float2(v.z - f1.x, v.w - f1.y));
    B2U a, b, c, d; a.b = h0; b.b = h1; c.b = l0; d.b = l1;
    *(uint2*)(sm + SM_XH + sw) = make_uint2(a.u, b.u);
    *(uint2*)(sm + SM_XL + sw) = make_uint2(c.u, d.u);
}

// ---------------------------------------------------------------------------
// Unified 3-term GEMM for both denses, single k-loop. NI=2 row blocks of 16.
// Weight tiles at smem 0 / 32768 / 65536 / 98304 (aH, aL, bH, bL).
// ---------------------------------------------------------------------------
__device__ __forceinline__ void gemm_uni(uint32_t smb, int mBase, int nBase,
                                         int r, int q,
                                         float (&accA)[2][4][4], float (&accB)[2][4][4]) {
    const uint32_t XH = smb + SM_XH, XL = smb + SM_XL;
    const int cA = q >> 1, cB = q & 1;
    const uint32_t rowA0 = (uint32_t)(mBase + r + 8 * (q & 1));
    const uint32_t rowB  = (uint32_t)(r + 8 * (q >> 1));
#pragma unroll
    for (int k0 = 0; k0 < 128; k0 += 16) {
        const int kc = k0 >> 3;
        const uint32_t offA = (rowA0 << 8) + ((uint32_t)((cA + kc) ^ r) << 4);
        uint32_t Ah[2][4], Al[2][4];
#pragma unroll
        for (int i = 0; i < 2; i++) {
            ldmx4(Ah[i], XH + offA + (uint32_t)(i << 12));
            ldmx4(Al[i], XL + offA + (uint32_t)(i << 12));
        }
#pragma unroll
        for (int j2 = 0; j2 < 2; j2++) {
            const uint32_t offB = ((uint32_t)(nBase + 16 * j2 + rowB) << 8)
                                + ((uint32_t)((cB + kc) ^ r) << 4);
            uint32_t paH[4], paL[4], pbH[4], pbL[4];
            ldmx4(paH, smb + offB);
            ldmx4(paL, smb + 32768 + offB);
            ldmx4(pbH, smb + 65536 + offB);
            ldmx4(pbL, smb + 98304 + offB);
#pragma unroll
            for (int jj = 0; jj < 2; jj++) {
                const int j = 2 * j2 + jj;
#pragma unroll
                for (int i = 0; i < 2; i++) {
                    mma16816(accA[i][j], Ah[i], paH[2 * jj], paH[2 * jj + 1]);
                    mma16816(accA[i][j], Ah[i], paL[2 * jj], paL[2 * jj + 1]);
                    mma16816(accA[i][j], Al[i], paH[2 * jj], paH[2 * jj + 1]);
                    mma16816(accB[i][j], Ah[i], pbH[2 * jj], pbH[2 * jj + 1]);
                    mma16816(accB[i][j], Ah[i], pbL[2 * jj], pbL[2 * jj + 1]);
                    mma16816(accB[i][j], Al[i], pbH[2 * jj], pbH[2 * jj + 1]);
                }
            }
        }
    }
}

// Stage helpers: 64-row tile = 2048 float4. 8 per thread (same indices on
// fetch and convert, so per-thread wait_group 0 covers the data each thread
// converts; __syncthreads publishes to other warps).
__device__ __forceinline__ void stage_fetch(uint32_t smb, const float* __restrict__ src, int tid) {
#pragma unroll
    for (int qq = 0; qq < 8; qq++) {
        const int sidx = tid + qq * THREADS;
        cpa16(smb + SM_STG + (uint32_t)sidx * 16, src + (size_t)sidx * 4);
    }
    cpa_commit();
}
__device__ __forceinline__ void stage_convert(char* sm, int tid) {
    const float4* st = (const float4*)(sm + SM_STG);
#pragma unroll
    for (int qq = 0; qq < 8; qq++) {
        const int sidx = tid + qq * THREADS;
        x_store(sm, sidx, st[sidx]);
    }
}

// ---------------------------------------------------------------------------
// Weight prep (+ zero g_PS): B-orientation, hi/lo split, swizzled 256B rows.
// 512 blocks x 256 threads.
// ---------------------------------------------------------------------------
extern "C" __global__ void eaw_prep(const float* __restrict__ W1a, const float* __restrict__ W1b,
                                    const float* __restrict__ W2a, const float* __restrict__ W2b,
                                    const float* __restrict__ W3a, const float* __restrict__ W3b) {
    const int e = blockIdx.x * blockDim.x + threadIdx.x;
    ((float4*)g_PS)[e]          = make_float4(0.f, 0.f, 0.f, 0.f);
    ((float4*)g_PS)[e + 131072] = make_float4(0.f, 0.f, 0.f, 0.f);

    int mat, off;
    if (e < 65536) { mat = e >> 14; off = e & 16383; }
    else           { int e2 = e - 65536; mat = 4 + (e2 >> 15); off = e2 & 32767; }
    const float* W;
    switch (mat) {
        case 0: W = W2a; break; case 1: W = W2b; break;
        case 2: W = W1a; break; case 3: W = W1b; break;
        case 4: W = W3a; break; default: W = W3b; break;
    }
    const int n = off & 127, k = off >> 7;     // W[k][n] at W[off] (coalesced)
    const float v = W[off];
    const __nv_bfloat16 h  = __float2bfloat16(v);
    const __nv_bfloat16 lo = __float2bfloat16(v - __bfloat162float(h));
    const int p = k >> 7, kk = k & 127;
    int hiTile;
    switch (mat) {
        case 0: hiTile = 0; break; case 1: hiTile = 2; break;
        case 2: hiTile = 4; break; case 3: hiTile = 6; break;
        case 4: hiTile = 8 + 4 * p;  break;
        default: hiTile = 10 + 4 * p; break;
    }
    const size_t pos = ((size_t)n << 8) + ((size_t)((kk >> 3) ^ (n & 7)) << 4) + ((size_t)(kk & 7) << 1);
    *(__nv_bfloat16*)(g_Wp + (size_t)hiTile * TILEB + pos)       = h;
    *(__nv_bfloat16*)(g_Wp + (size_t)(hiTile + 1) * TILEB + pos) = lo;
}

// ---------------------------------------------------------------------------
// Pair branch (persistent, M=64 tiles): relu(t2*(FP@W2a+b2a)*(FP@W2b+b2b))
// scatter-added into g_PS. X pipelined: cp.async stage -> convert -> gemm.
// ---------------------------------------------------------------------------
extern "C" __global__ void __launch_bounds__(THREADS, 1)
eaw_pair_mm(const float* __restrict__ FP, const int* __restrict__ split,
            const float* __restrict__ b2a, const float* __restrict__ b2b,
            const float* __restrict__ t2, int nTiles) {
    extern __shared__ __align__(1024) char sm[];
    const int tid = threadIdx.x;
    const uint32_t smb = smem_u32(sm);

    {   // weights: 4 tiles (131072B) linear copy
        const uint4* src = (const uint4*)g_Wp;
        uint4* dst = (uint4*)sm;
        for (int i = tid; i < 8192; i += THREADS) dst[i] = src[i];
    }
    if (tid < 128) {
        ((float*)(sm + SM_BIAS))[tid]       = b2a[tid];
        ((float*)(sm + SM_BIAS))[128 + tid] = b2b[tid];
        ((float*)(sm + SM_BIAS))[256 + tid] = t2[tid];
    }

    const int lane = tid & 31, w = tid >> 5;
    const int mBase = (w >> 2) * 32, nBase = (w & 3) * 32;
    const int q = lane >> 3, r = lane & 7;
    const float* biasA = (const float*)(sm + SM_BIAS);
    const float* biasB = biasA + 128;
    const float* tvv   = biasA + 256;
    const int grid = gridDim.x;

    // prologue: X(tile0) through stage, prefetch X(tile0+grid)
    int tile = blockIdx.x;
    stage_fetch(smb, FP + (size_t)tile * (TILE_M * F), tid);
    cpa_wait0();
    stage_convert(sm, tid);
    if (tile + grid < nTiles) stage_fetch(smb, FP + (size_t)(tile + grid) * (TILE_M * F), tid);
    __syncthreads();

    for (; tile < nTiles; tile += grid) {
        float accA[2][4][4], accB[2][4][4];
#pragma unroll
        for (int i = 0; i < 2; i++)
#pragma unroll
            for (int j = 0; j < 4; j++)
#pragma unroll
                for (int kq = 0; kq < 4; kq++) { accA[i][j][kq] = 0.f; accB[i][j][kq] = 0.f; }

        gemm_uni(smb, mBase, nBase, r, q, accA, accB);

        // epilogue (registers + gmem only; does not touch XH/XL)
        const int* sp = split + tile * TILE_M;
#pragma unroll
        for (int i = 0; i < 2; i++) {
#pragma unroll
            for (int sub = 0; sub < 2; sub++) {
                const int row = mBase + 16 * i + (lane >> 2) + 8 * sub;
                const int atom = sp[row];
                float* dst = g_PS + (size_t)atom * F;
#pragma unroll
                for (int j = 0; j < 4; j++) {
                    const int c = nBase + 8 * j + 2 * (lane & 3);
                    const float v0 = fmaxf(tvv[c]     * (accA[i][j][2 * sub]     + biasA[c])     * (accB[i][j][2 * sub]     + biasB[c]),     0.f);
                    const float v1 = fmaxf(tvv[c + 1] * (accA[i][j][2 * sub + 1] + biasA[c + 1]) * (accB[i][j][2 * sub + 1] + biasB[c + 1]), 0.f);
                    red_v2(dst + c, v0, v1);
                }
            }
        }

        const int nt = tile + grid;
        __syncthreads();                    // all XH/XL reads of this tile done
        if (nt < nTiles) {
            cpa_wait0();                    // X(nt) staged
            stage_convert(sm, tid);         // stage -> XH/XL
        }
        __syncthreads();                    // converts visible; stage free
        if (nt + grid < nTiles)
            stage_fetch(smb, FP + (size_t)(nt + grid) * (TILE_M * F), tid);
    }
}

// ---------------------------------------------------------------------------
// Atom layer 1: g_AA = relu(t1*(FA@W1a+b1a)*(FA@W1b+b1b)). 128 CTAs x 64 rows.
// ---------------------------------------------------------------------------
extern "C" __global__ void __launch_bounds__(THREADS, 1)
eaw_atom1_mm(const float* __restrict__ FA,
             const float* __restrict__ b1a, const float* __restrict__ b1b,
             const float* __restrict__ t1) {
    extern __shared__ __align__(1024) char sm[];
    const int tid = threadIdx.x;
    const uint32_t smb = smem_u32(sm);
    {
        const uint4* src = (const uint4*)(g_Wp + 4 * TILEB);
        uint4* dst = (uint4*)sm;
        for (int i = tid; i < 8192; i += THREADS) dst[i] = src[i];
    }
    if (tid < 128) {
        ((float*)(sm + SM_BIAS))[tid]       = b1a[tid];
        ((float*)(sm + SM_BIAS))[128 + tid] = b1b[tid];
        ((float*)(sm + SM_BIAS))[256 + tid] = t1[tid];
    }
    {   // X: 64 rows = 2048 float4 (8 per thread)
        const float4* src = (const float4*)(FA + (size_t)blockIdx.x * (TILE_M * F));
        float4 xv[8];
#pragma unroll
        for (int qq = 0; qq < 8; qq++) xv[qq] = src[tid + qq * THREADS];
#pragma unroll
        for (int qq = 0; qq < 8; qq++) x_store(sm, tid + qq * THREADS, xv[qq]);
    }
    __syncthreads();

    const int lane = tid & 31, w = tid >> 5;
    const int mBase = (w >> 2) * 32, nBase = (w & 3) * 32;
    const int q = lane >> 3, r = lane & 7;
    const float* biasA = (const float*)(sm + SM_BIAS);
    const float* biasB = biasA + 128;
    const float* tvv   = biasA + 256;

    float accA[2][4][4], accB[2][4][4];
#pragma unroll
    for (int i = 0; i < 2; i++)
#pragma unroll
        for (int j = 0; j < 4; j++)
#pragma unroll
            for (int kq = 0; kq < 4; kq++) { accA[i][j][kq] = 0.f; accB[i][j][kq] = 0.f; }

    gemm_uni(smb, mBase, nBase, r, q, accA, accB);

    float* base = g_AA + (size_t)blockIdx.x * (TILE_M * F);
#pragma unroll
    for (int i = 0; i < 2; i++) {
#pragma unroll
        for (int sub = 0; sub < 2; sub++) {
            const int row = mBase + 16 * i + (lane >> 2) + 8 * sub;
#pragma unroll
            for (int j = 0; j < 4; j++) {
                const int c = nBase + 8 * j + 2 * (lane & 3);
                float2 v;
                v.x = fmaxf(tvv[c]     * (accA[i][j][2 * sub]     + biasA[c])     * (accB[i][j][2 * sub]     + biasB[c]),     0.f);
                v.y = fmaxf(tvv[c + 1] * (accA[i][j][2 * sub + 1] + biasA[c + 1]) * (accB[i][j][2 * sub + 1] + biasB[c + 1]), 0.f);
                *(float2*)(base + (size_t)row * F + c) = v;
            }
        }
    }
}

// ---------------------------------------------------------------------------
// Final layer (K=256, two phases): out = relu(t3*([AA|PS]@W3a+b3a)*(...b)).
// 128 CTAs x 64 rows.
// ---------------------------------------------------------------------------
extern "C" __global__ void __launch_bounds__(THREADS, 1)
eaw_atom2_mm(const float* __restrict__ b3a, const float* __restrict__ b3b,
             const float* __restrict__ t3, float* __restrict__ out) {
    extern __shared__ __align__(1024) char sm[];
    const int tid = threadIdx.x;
    const uint32_t smb = smem_u32(sm);
    if (tid < 128) {
        ((float*)(sm + SM_BIAS))[tid]       = b3a[tid];
        ((float*)(sm + SM_BIAS))[128 + tid] = b3b[tid];
        ((float*)(sm + SM_BIAS))[256 + tid] = t3[tid];
    }
    const int lane = tid & 31, w = tid >> 5;
    const int mBase = (w >> 2) * 32, nBase = (w & 3) * 32;
    const int q = lane >> 3, r = lane & 7;
    const float* biasA = (const float*)(sm + SM_BIAS);
    const float* biasB = biasA + 128;
    const float* tvv   = biasA + 256;

    float accA[2][4][4], accB[2][4][4];
#pragma unroll
    for (int i = 0; i < 2; i++)
#pragma unroll
        for (int j = 0; j < 4; j++)
#pragma unroll
            for (int kq = 0; kq < 4; kq++) { accA[i][j][kq] = 0.f; accB[i][j][kq] = 0.f; }

#pragma unroll 1
    for (int p = 0; p < 2; p++) {
        if (p) __syncthreads();             // previous phase's smem reads done
        {
            const uint4* src = (const uint4*)(g_Wp + (size_t)(8 + 4 * p) * TILEB);
            uint4* dst = (uint4*)sm;
            for (int i = tid; i < 8192; i += THREADS) dst[i] = src[i];
        }
        {
            const float4* src = (const float4*)((p == 0 ? g_AA : g_PS) + (size_t)blockIdx.x * (TILE_M * F));
            float4 xv[8];
#pragma unroll
            for (int qq = 0; qq < 8; qq++) xv[qq] = src[tid + qq * THREADS];
#pragma unroll
            for (int qq = 0; qq < 8; qq++) x_store(sm, tid + qq * THREADS, xv[qq]);
        }
        __syncthreads();
        gemm_uni(smb, mBase, nBase, r, q, accA, accB);
    }

    float* base = out + (size_t)blockIdx.x * (TILE_M * F);
#pragma unroll
    for (int i = 0; i < 2; i++) {
#pragma unroll
        for (int sub = 0; sub < 2; sub++) {
            const int row = mBase + 16 * i + (lane >> 2) + 8 * sub;
#pragma unroll
            for (int j = 0; j < 4; j++) {
                const int c = nBase + 8 * j + 2 * (lane & 3);
                float2 v;
                v.x = fmaxf(tvv[c]     * (accA[i][j][2 * sub]     + biasA[c])     * (accB[i][j][2 * sub]     + biasB[c]),     0.f);
                v.y = fmaxf(tvv[c + 1] * (accA[i][j][2 * sub + 1] + biasA[c + 1]) * (accB[i][j][2 * sub + 1] + biasB[c + 1]), 0.f);
                *(float2*)(base + (size_t)row * F + c) = v;
            }
        }
    }
}

// ---------------------------------------------------------------------------
// Launch
// ---------------------------------------------------------------------------
extern "C" void kernel_launch(void* const* d_in, const int* in_sizes, int n_in,
                              void* d_out, int out_size) {
    const float* FA  = (const float*)d_in[0];
    const float* FP  = (const float*)d_in[1];
    const int*   sp  = (const int*)  d_in[2];
    const float* W1a = (const float*)d_in[3];
    const float* b1a = (const float*)d_in[4];
    const float* W1b = (const float*)d_in[5];
    const float* b1b = (const float*)d_in[6];
    const float* t1  = (const float*)d_in[7];
    const float* W2a = (const float*)d_in[8];
    const float* b2a = (const float*)d_in[9];
    const float* W2b = (const float*)d_in[10];
    const float* b2b = (const float*)d_in[11];
    const float* t2  = (const float*)d_in[12];
    const float* W3a = (const float*)d_in[13];
    const float* b3a = (const float*)d_in[14];
    const float* W3b = (const float*)d_in[15];
    const float* b3b = (const float*)d_in[16];
    const float* t3  = (const float*)d_in[17];
    float* out = (float*)d_out;

    const int nPairs    = in_sizes[1] / F;       // 524288
    const int pairTiles = nPairs / TILE_M;       // 8192
    const int atomTiles = (in_sizes[0] / F) / TILE_M;  // 128

    cudaFuncSetAttribute(eaw_pair_mm,  cudaFuncAttributeMaxDynamicSharedMemorySize, SMEM_BYTES);
    cudaFuncSetAttribute(eaw_atom1_mm, cudaFuncAttributeMaxDynamicSharedMemorySize, SMEM_BYTES);
    cudaFuncSetAttribute(eaw_atom2_mm, cudaFuncAttributeMaxDynamicSharedMemorySize, SMEM_BYTES);

    int nsm = 148;
    cudaDeviceGetAttribute(&nsm, cudaDevAttrMultiProcessorCount, 0);

    eaw_prep<<<512, 256>>>(W1a, W1b, W2a, W2b, W3a, W3b);
    eaw_pair_mm<<<nsm, THREADS, SMEM_BYTES>>>(FP, sp, b2a, b2b, t2, pairTiles);
    eaw_atom1_mm<<<atomTiles, THREADS, SMEM_BYTES>>>(FA, b1a, b1b, t1);
    eaw_atom2_mm<<<atomTiles, THREADS, SMEM_BYTES>>>(b3a, b3b, t3, out);
}

// round 7
// speedup vs baseline: 2.9522x; 1.1076x over previous
#include <cuda_runtime.h>
#include <cuda_bf16.h>
#include <cstdint>

#define F        128
#define THREADS  512
#define N_ATOMS  8192
#define TILE_M   64
#define TILEB    32768        // weight tile: 128 rows * 256B (bf16, swizzled)

// ---------------------------------------------------------------------------
// Device-global scratch (no allocations allowed)
// ---------------------------------------------------------------------------
__device__ float g_PS[N_ATOMS * F];   // segment-summed pair activations
__device__ float g_AA[N_ATOMS * F];   // atom layer-1 output
// Prepped weights: bf16, B-orientation [n][k], 256B rows, XOR-swizzled chunks,
// hi/lo split. 16 tiles of 32768B:
//  0:W2aH 1:W2aL 2:W2bH 3:W2bL  4:W1aH 5:W1aL 6:W1bH 7:W1bL
//  8..11: W3 chunk0 (aH,aL,bH,bL)  12..15: W3 chunk1
__device__ __align__(256) unsigned char g_Wp[16 * TILEB];

// SMEM map (dynamic, base 1024-aligned):
//  [0,131072)        4 weight tiles (aH, aL, bH, bL)
//  [131072,147456)   X hi bf16 (64 rows x 256B)
//  [147456,163840)   X lo bf16
//  [163840,196608)   fp32 stage (64 rows x 128 fp32 = 32KB)
//  [196608,198144)   bias: ba[128], bb[128], t[128]
#define SM_XH    131072
#define SM_XL    147456
#define SM_STG   163840
#define SM_BIAS  196608
#define SMEM_BYTES 198144

// ---------------------------------------------------------------------------
// PTX helpers (baseline ISA: ldmatrix, mma.sync, cp.async, red)
// ---------------------------------------------------------------------------
__device__ __forceinline__ uint32_t smem_u32(const void* p) {
    uint32_t a;
    asm("{ .reg .u64 t; cvta.to.shared.u64 t, %1; cvt.u32.u64 %0, t; }" : "=r"(a) : "l"(p));
    return a;
}
__device__ __forceinline__ void ldmx4(uint32_t* r, uint32_t addr) {
    asm volatile("ldmatrix.sync.aligned.m8n8.x4.shared.b16 {%0,%1,%2,%3}, [%4];"
                 : "=r"(r[0]), "=r"(r[1]), "=r"(r[2]), "=r"(r[3]) : "r"(addr));
}
__device__ __forceinline__ void mma16816(float* d, const uint32_t* a, uint32_t b0, uint32_t b1) {
    asm volatile(
        "mma.sync.aligned.m16n8k16.row.col.f32.bf16.bf16.f32 "
        "{%0,%1,%2,%3}, {%4,%5,%6,%7}, {%8,%9}, {%0,%1,%2,%3};"
        : "+f"(d[0]), "+f"(d[1]), "+f"(d[2]), "+f"(d[3])
        : "r"(a[0]), "r"(a[1]), "r"(a[2]), "r"(a[3]), "r"(b0), "r"(b1));
}
__device__ __forceinline__ void red_v2(float* addr, float a, float b) {
    asm volatile("red.global.add.v2.f32 [%0], {%1,%2};"
                 :: "l"(addr), "f"(a), "f"(b) : "memory");
}
__device__ __forceinline__ void cpa16(uint32_t saddr, const void* g) {
    asm volatile("cp.async.cg.shared.global [%0], [%1], 16;" :: "r"(saddr), "l"(g));
}
__device__ __forceinline__ void cpa_commit() {
    asm volatile("cp.async.commit_group;" ::: "memory");
}
__device__ __forceinline__ void cpa_wait0() {
    asm volatile("cp.async.wait_group 0;" ::: "memory");
}

// ---------------------------------------------------------------------------
// X element store: fp32 float4 -> bf16 hi/lo at swizzled (row m, k4).
// i = float4 index in [0,2048): m = i>>5 in [0,64), k4 = (i&31)*4.
// Layout: 256B rows; 16B chunk c holds k in [8c,8c+8) at chunk (c ^ (m&7)).
// ---------------------------------------------------------------------------
union B2U { __nv_bfloat162 b; uint32_t u; };

__device__ __forceinline__ void x_store(char* sm, int i, float4 v) {
    const int m = i >> 5, k4 = (i & 31) << 2;
    const uint32_t sw = (uint32_t)(m << 8) + ((uint32_t)(((k4 >> 3) ^ (m & 7))) << 4)
                      + ((uint32_t)((k4 >> 2) & 1) << 3);
    __nv_bfloat162 h0 = __float22bfloat162_rn(make_float2(v.x, v.y));
    __nv_bfloat162 h1 = __float22bfloat162_rn(make_float2(v.z, v.w));
    float2 f0 = __bfloat1622float2(h0), f1 = __bfloat1622float2(h1);
    __nv_bfloat162 l0 = __float22bfloat162_rn(make_float2(v.x - f0.x, v.y - f0.y));
    __nv_bfloat162 l1 = __float22bfloat162_rn(make_float2(v.z - f1.x, v.w - f1.y));
    B2U a, b, c, d; a.b = h0; b.b = h1; c.b = l0; d.b = l1;
    *(uint2*)(sm + SM_XH + sw) = make_uint2(a.u, b.u);
    *(uint2*)(sm + SM_XL + sw) = make_uint2(c.u, d.u);
}

// ---------------------------------------------------------------------------
// Unified 3-term GEMM for both denses, single k-loop. 16 warps, patch 16x32.
// Weight tiles at smem 0 / 32768 / 65536 / 98304 (aH, aL, bH, bL).
// ---------------------------------------------------------------------------
__device__ __forceinline__ void gemm_uni(uint32_t smb, int mBase, int nBase,
                                         int r, int q,
                                         float (&accA)[4][4], float (&accB)[4][4]) {
    const uint32_t XH = smb + SM_XH, XL = smb + SM_XL;
    const int cA = q >> 1, cB = q & 1;
    const uint32_t rowA0 = (uint32_t)(mBase + r + 8 * (q & 1));
    const uint32_t rowB  = (uint32_t)(r + 8 * (q >> 1));
#pragma unroll
    for (int k0 = 0; k0 < 128; k0 += 16) {
        const int kc = k0 >> 3;
        const uint32_t offA = (rowA0 << 8) + ((uint32_t)((cA + kc) ^ r) << 4);
        uint32_t Ah[4], Al[4];
        ldmx4(Ah, XH + offA);
        ldmx4(Al, XL + offA);
#pragma unroll
        for (int j2 = 0; j2 < 2; j2++) {
            const uint32_t offB = ((uint32_t)(nBase + 16 * j2 + rowB) << 8)
                                + ((uint32_t)((cB + kc) ^ r) << 4);
            uint32_t paH[4], paL[4], pbH[4], pbL[4];
            ldmx4(paH, smb + offB);
            ldmx4(paL, smb + 32768 + offB);
            ldmx4(pbH, smb + 65536 + offB);
            ldmx4(pbL, smb + 98304 + offB);
#pragma unroll
            for (int jj = 0; jj < 2; jj++) {
                const int j = 2 * j2 + jj;
                mma16816(accA[j], Ah, paH[2 * jj], paH[2 * jj + 1]);
                mma16816(accA[j], Ah, paL[2 * jj], paL[2 * jj + 1]);
                mma16816(accA[j], Al, paH[2 * jj], paH[2 * jj + 1]);
                mma16816(accB[j], Ah, pbH[2 * jj], pbH[2 * jj + 1]);
                mma16816(accB[j], Ah, pbL[2 * jj], pbL[2 * jj + 1]);
                mma16816(accB[j], Al, pbH[2 * jj], pbH[2 * jj + 1]);
            }
        }
    }
}

// Stage helpers: 64-row tile = 2048 float4, 4 per thread (same indices on
// fetch and convert so per-thread wait_group 0 covers converted data;
// __syncthreads publishes to other warps).
__device__ __forceinline__ void stage_fetch(uint32_t smb, const float* __restrict__ src, int tid) {
#pragma unroll
    for (int qq = 0; qq < 4; qq++) {
        const int sidx = tid + qq * THREADS;
        cpa16(smb + SM_STG + (uint32_t)sidx * 16, src + (size_t)sidx * 4);
    }
    cpa_commit();
}
__device__ __forceinline__ void stage_convert(char* sm, int tid) {
    const float4* st = (const float4*)(sm + SM_STG);
#pragma unroll
    for (int qq = 0; qq < 4; qq++) {
        const int sidx = tid + qq * THREADS;
        x_store(sm, sidx, st[sidx]);
    }
}

// ---------------------------------------------------------------------------
// Weight prep (+ zero g_PS): B-orientation, hi/lo split, swizzled 256B rows.
// 512 blocks x 256 threads.
// ---------------------------------------------------------------------------
extern "C" __global__ void eaw_prep(const float* __restrict__ W1a, const float* __restrict__ W1b,
                                    const float* __restrict__ W2a, const float* __restrict__ W2b,
                                    const float* __restrict__ W3a, const float* __restrict__ W3b) {
    const int e = blockIdx.x * blockDim.x + threadIdx.x;
    ((float4*)g_PS)[e]          = make_float4(0.f, 0.f, 0.f, 0.f);
    ((float4*)g_PS)[e + 131072] = make_float4(0.f, 0.f, 0.f, 0.f);

    int mat, off;
    if (e < 65536) { mat = e >> 14; off = e & 16383; }
    else           { int e2 = e - 65536; mat = 4 + (e2 >> 15); off = e2 & 32767; }
    const float* W;
    switch (mat) {
        case 0: W = W2a; break; case 1: W = W2b; break;
        case 2: W = W1a; break; case 3: W = W1b; break;
        case 4: W = W3a; break; default: W = W3b; break;
    }
    const int n = off & 127, k = off >> 7;     // W[k][n] at W[off] (coalesced)
    const float v = W[off];
    const __nv_bfloat16 h  = __float2bfloat16(v);
    const __nv_bfloat16 lo = __float2bfloat16(v - __bfloat162float(h));
    const int p = k >> 7, kk = k & 127;
    int hiTile;
    switch (mat) {
        case 0: hiTile = 0; break; case 1: hiTile = 2; break;
        case 2: hiTile = 4; break; case 3: hiTile = 6; break;
        case 4: hiTile = 8 + 4 * p;  break;
        default: hiTile = 10 + 4 * p; break;
    }
    const size_t pos = ((size_t)n << 8) + ((size_t)((kk >> 3) ^ (n & 7)) << 4) + ((size_t)(kk & 7) << 1);
    *(__nv_bfloat16*)(g_Wp + (size_t)hiTile * TILEB + pos)       = h;
    *(__nv_bfloat16*)(g_Wp + (size_t)(hiTile + 1) * TILEB + pos) = lo;
}

// ---------------------------------------------------------------------------
// Pair branch (persistent, M=64 tiles, 16 warps): scatter-add into g_PS.
// X pipelined: cp.async stage -> convert -> gemm.
// ---------------------------------------------------------------------------
extern "C" __global__ void __launch_bounds__(THREADS, 1)
eaw_pair_mm(const float* __restrict__ FP, const int* __restrict__ split,
            const float* __restrict__ b2a, const float* __restrict__ b2b,
            const float* __restrict__ t2, int nTiles) {
    extern __shared__ __align__(1024) char sm[];
    const int tid = threadIdx.x;
    const uint32_t smb = smem_u32(sm);

    {   // weights: 4 tiles (131072B) linear copy
        const uint4* src = (const uint4*)g_Wp;
        uint4* dst = (uint4*)sm;
        for (int i = tid; i < 8192; i += THREADS) dst[i] = src[i];
    }
    if (tid < 128) {
        ((float*)(sm + SM_BIAS))[tid]       = b2a[tid];
        ((float*)(sm + SM_BIAS))[128 + tid] = b2b[tid];
        ((float*)(sm + SM_BIAS))[256 + tid] = t2[tid];
    }

    const int lane = tid & 31, w = tid >> 5;
    const int mBase = (w >> 2) * 16, nBase = (w & 3) * 32;
    const int q = lane >> 3, r = lane & 7;
    const float* biasA = (const float*)(sm + SM_BIAS);
    const float* biasB = biasA + 128;
    const float* tvv   = biasA + 256;
    const int grid = gridDim.x;

    // prologue: X(tile0) through stage, prefetch X(tile0+grid)
    int tile = blockIdx.x;
    stage_fetch(smb, FP + (size_t)tile * (TILE_M * F), tid);
    cpa_wait0();
    stage_convert(sm, tid);
    if (tile + grid < nTiles) stage_fetch(smb, FP + (size_t)(tile + grid) * (TILE_M * F), tid);
    __syncthreads();

    for (; tile < nTiles; tile += grid) {
        float accA[4][4], accB[4][4];
#pragma unroll
        for (int j = 0; j < 4; j++)
#pragma unroll
            for (int kq = 0; kq < 4; kq++) { accA[j][kq] = 0.f; accB[j][kq] = 0.f; }

        gemm_uni(smb, mBase, nBase, r, q, accA, accB);

        // epilogue (registers + gmem only; does not touch XH/XL)
        const int* sp = split + tile * TILE_M;
#pragma unroll
        for (int sub = 0; sub < 2; sub++) {
            const int row = mBase + (lane >> 2) + 8 * sub;
            const int atom = sp[row];
            float* dst = g_PS + (size_t)atom * F;
#pragma unroll
            for (int j = 0; j < 4; j++) {
                const int c = nBase + 8 * j + 2 * (lane & 3);
                const float v0 = fmaxf(tvv[c]     * (accA[j][2 * sub]     + biasA[c])     * (accB[j][2 * sub]     + biasB[c]),     0.f);
                const float v1 = fmaxf(tvv[c + 1] * (accA[j][2 * sub + 1] + biasA[c + 1]) * (accB[j][2 * sub + 1] + biasB[c + 1]), 0.f);
                red_v2(dst + c, v0, v1);
            }
        }

        const int nt = tile + grid;
        __syncthreads();                    // all XH/XL reads of this tile done
        if (nt < nTiles) {
            cpa_wait0();                    // X(nt) staged
            stage_convert(sm, tid);         // stage -> XH/XL
        }
        __syncthreads();                    // converts visible; stage free
        if (nt + grid < nTiles)
            stage_fetch(smb, FP + (size_t)(nt + grid) * (TILE_M * F), tid);
    }
}

// ---------------------------------------------------------------------------
// Atom layer 1: g_AA = relu(t1*(FA@W1a+b1a)*(FA@W1b+b1b)). 128 CTAs x 64 rows.
// ---------------------------------------------------------------------------
extern "C" __global__ void __launch_bounds__(THREADS, 1)
eaw_atom1_mm(const float* __restrict__ FA,
             const float* __restrict__ b1a, const float* __restrict__ b1b,
             const float* __restrict__ t1) {
    extern __shared__ __align__(1024) char sm[];
    const int tid = threadIdx.x;
    const uint32_t smb = smem_u32(sm);
    {
        const uint4* src = (const uint4*)(g_Wp + 4 * TILEB);
        uint4* dst = (uint4*)sm;
        for (int i = tid; i < 8192; i += THREADS) dst[i] = src[i];
    }
    if (tid < 128) {
        ((float*)(sm + SM_BIAS))[tid]       = b1a[tid];
        ((float*)(sm + SM_BIAS))[128 + tid] = b1b[tid];
        ((float*)(sm + SM_BIAS))[256 + tid] = t1[tid];
    }
    {   // X: 64 rows = 2048 float4 (4 per thread)
        const float4* src = (const float4*)(FA + (size_t)blockIdx.x * (TILE_M * F));
        float4 xv[4];
#pragma unroll
        for (int qq = 0; qq < 4; qq++) xv[qq] = src[tid + qq * THREADS];
#pragma unroll
        for (int qq = 0; qq < 4; qq++) x_store(sm, tid + qq * THREADS, xv[qq]);
    }
    __syncthreads();

    const int lane = tid & 31, w = tid >> 5;
    const int mBase = (w >> 2) * 16, nBase = (w & 3) * 32;
    const int q = lane >> 3, r = lane & 7;
    const float* biasA = (const float*)(sm + SM_BIAS);
    const float* biasB = biasA + 128;
    const float* tvv   = biasA + 256;

    float accA[4][4], accB[4][4];
#pragma unroll
    for (int j = 0; j < 4; j++)
#pragma unroll
        for (int kq = 0; kq < 4; kq++) { accA[j][kq] = 0.f; accB[j][kq] = 0.f; }

    gemm_uni(smb, mBase, nBase, r, q, accA, accB);

    float* base = g_AA + (size_t)blockIdx.x * (TILE_M * F);
#pragma unroll
    for (int sub = 0; sub < 2; sub++) {
        const int row = mBase + (lane >> 2) + 8 * sub;
#pragma unroll
        for (int j = 0; j < 4; j++) {
            const int c = nBase + 8 * j + 2 * (lane & 3);
            float2 v;
            v.x = fmaxf(tvv[c]     * (accA[j][2 * sub]     + biasA[c])     * (accB[j][2 * sub]     + biasB[c]),     0.f);
            v.y = fmaxf(tvv[c + 1] * (accA[j][2 * sub + 1] + biasA[c + 1]) * (accB[j][2 * sub + 1] + biasB[c + 1]), 0.f);
            *(float2*)(base + (size_t)row * F + c) = v;
        }
    }
}

// ---------------------------------------------------------------------------
// Final layer (K=256, two phases): out = relu(t3*([AA|PS]@W3a+b3a)*(...b)).
// 128 CTAs x 64 rows.
// ---------------------------------------------------------------------------
extern "C" __global__ void __launch_bounds__(THREADS, 1)
eaw_atom2_mm(const float* __restrict__ b3a, const float* __restrict__ b3b,
             const float* __restrict__ t3, float* __restrict__ out) {
    extern __shared__ __align__(1024) char sm[];
    const int tid = threadIdx.x;
    const uint32_t smb = smem_u32(sm);
    if (tid < 128) {
        ((float*)(sm + SM_BIAS))[tid]       = b3a[tid];
        ((float*)(sm + SM_BIAS))[128 + tid] = b3b[tid];
        ((float*)(sm + SM_BIAS))[256 + tid] = t3[tid];
    }
    const int lane = tid & 31, w = tid >> 5;
    const int mBase = (w >> 2) * 16, nBase = (w & 3) * 32;
    const int q = lane >> 3, r = lane & 7;
    const float* biasA = (const float*)(sm + SM_BIAS);
    const float* biasB = biasA + 128;
    const float* tvv   = biasA + 256;

    float accA[4][4], accB[4][4];
#pragma unroll
    for (int j = 0; j < 4; j++)
#pragma unroll
        for (int kq = 0; kq < 4; kq++) { accA[j][kq] = 0.f; accB[j][kq] = 0.f; }

#pragma unroll 1
    for (int p = 0; p < 2; p++) {
        if (p) __syncthreads();             // previous phase's smem reads done
        {
            const uint4* src = (const uint4*)(g_Wp + (size_t)(8 + 4 * p) * TILEB);
            uint4* dst = (uint4*)sm;
            for (int i = tid; i < 8192; i += THREADS) dst[i] = src[i];
        }
        {
            const float4* src = (const float4*)((p == 0 ? g_AA : g_PS) + (size_t)blockIdx.x * (TILE_M * F));
            float4 xv[4];
#pragma unroll
            for (int qq = 0; qq < 4; qq++) xv[qq] = src[tid + qq * THREADS];
#pragma unroll
            for (int qq = 0; qq < 4; qq++) x_store(sm, tid + qq * THREADS, xv[qq]);
        }
        __syncthreads();
        gemm_uni(smb, mBase, nBase, r, q, accA, accB);
    }

    float* base = out + (size_t)blockIdx.x * (TILE_M * F);
#pragma unroll
    for (int sub = 0; sub < 2; sub++) {
        const int row = mBase + (lane >> 2) + 8 * sub;
#pragma unroll
        for (int j = 0; j < 4; j++) {
            const int c = nBase + 8 * j + 2 * (lane & 3);
            float2 v;
            v.x = fmaxf(tvv[c]     * (accA[j][2 * sub]     + biasA[c])     * (accB[j][2 * sub]     + biasB[c]),     0.f);
            v.y = fmaxf(tvv[c + 1] * (accA[j][2 * sub + 1] + biasA[c + 1]) * (accB[j][2 * sub + 1] + biasB[c + 1]), 0.f);
            *(float2*)(base + (size_t)row * F + c) = v;
        }
    }
}

// ---------------------------------------------------------------------------
// Launch
// ---------------------------------------------------------------------------
extern "C" void kernel_launch(void* const* d_in, const int* in_sizes, int n_in,
                              void* d_out, int out_size) {
    const float* FA  = (const float*)d_in[0];
    const float* FP  = (const float*)d_in[1];
    const int*   sp  = (const int*)  d_in[2];
    const float* W1a = (const float*)d_in[3];
    const float* b1a = (const float*)d_in[4];
    const float* W1b = (const float*)d_in[5];
    const float* b1b = (const float*)d_in[6];
    const float* t1  = (const float*)d_in[7];
    const float* W2a = (const float*)d_in[8];
    const float* b2a = (const float*)d_in[9];
    const float* W2b = (const float*)d_in[10];
    const float* b2b = (const float*)d_in[11];
    const float* t2  = (const float*)d_in[12];
    const float* W3a = (const float*)d_in[13];
    const float* b3a = (const float*)d_in[14];
    const float* W3b = (const float*)d_in[15];
    const float* b3b = (const float*)d_in[16];
    const float* t3  = (const float*)d_in[17];
    float* out = (float*)d_out;

    const int nPairs    = in_sizes[1] / F;             // 524288
    const int pairTiles = nPairs / TILE_M;             // 8192
    const int atomTiles = (in_sizes[0] / F) / TILE_M;  // 128

    cudaFuncSetAttribute(eaw_pair_mm,  cudaFuncAttributeMaxDynamicSharedMemorySize, SMEM_BYTES);
    cudaFuncSetAttribute(eaw_atom1_mm, cudaFuncAttributeMaxDynamicSharedMemorySize, SMEM_BYTES);
    cudaFuncSetAttribute(eaw_atom2_mm, cudaFuncAttributeMaxDynamicSharedMemorySize, SMEM_BYTES);

    int nsm = 148;
    cudaDeviceGetAttribute(&nsm, cudaDevAttrMultiProcessorCount, 0);

    eaw_prep<<<512, 256>>>(W1a, W1b, W2a, W2b, W3a, W3b);
    eaw_pair_mm<<<nsm, THREADS, SMEM_BYTES>>>(FP, sp, b2a, b2b, t2, pairTiles);
    eaw_atom1_mm<<<atomTiles, THREADS, SMEM_BYTES>>>(FA, b1a, b1b, t1);
    eaw_atom2_mm<<<atomTiles, THREADS, SMEM_BYTES>>>(b3a, b3b, t3, out);
}